// round 3
// baseline (speedup 1.0000x reference)
#include <cuda_runtime.h>
#include <math_constants.h>

#define NB  32
#define C   64
#define HW  1024
#define CHW 65536
#define EPS 1e-5f
#define JW  32      // j-stripe width per block

// ---------------- scratch (device globals; no allocations allowed) ----------
__device__ float g_qn[NB * CHW];
__device__ float g_kn[NB * CHW];
__device__ float g_vn[NB * CHW];
__device__ float g_q [NB * CHW];
__device__ float g_k [NB * CHW];
__device__ float g_v [NB * CHW];

// ---------------- 1. LayerNorm over full (C,H,W) per sample ----------------
__global__ __launch_bounds__(256) void ln_kernel(
    const float* __restrict__ q, const float* __restrict__ k, const float* __restrict__ v,
    const float* __restrict__ w1, const float* __restrict__ b1,
    const float* __restrict__ w2, const float* __restrict__ b2,
    const float* __restrict__ w3, const float* __restrict__ b3)
{
    int which = blockIdx.x % 3;
    int n     = blockIdx.x / 3;
    const float *x, *w, *b;
    float* dst;
    if (which == 0)      { x = q + n * CHW; w = w1; b = b1; dst = g_qn + n * CHW; }
    else if (which == 1) { x = k + n * CHW; w = w2; b = b2; dst = g_kn + n * CHW; }
    else                 { x = v + n * CHW; w = w3; b = b3; dst = g_vn + n * CHW; }

    int tid = threadIdx.x;
    float s = 0.f, ss = 0.f;
    for (int i = tid * 4; i < CHW; i += 256 * 4) {
        float4 val = *(const float4*)(x + i);
        s  += val.x + val.y + val.z + val.w;
        ss += val.x * val.x + val.y * val.y + val.z * val.z + val.w * val.w;
    }
    __shared__ float sm[256], sm2[256];
    sm[tid] = s; sm2[tid] = ss;
    __syncthreads();
    for (int o = 128; o > 0; o >>= 1) {
        if (tid < o) { sm[tid] += sm[tid + o]; sm2[tid] += sm2[tid + o]; }
        __syncthreads();
    }
    float mean = sm[0] * (1.0f / CHW);
    float var  = sm2[0] * (1.0f / CHW) - mean * mean;
    float rstd = rsqrtf(var + EPS);

    for (int i = tid * 4; i < CHW; i += 256 * 4) {
        float4 val = *(const float4*)(x + i);
        float4 wv  = *(const float4*)(w + i);
        float4 bv  = *(const float4*)(b + i);
        float4 o4;
        o4.x = (val.x - mean) * rstd * wv.x + bv.x;
        o4.y = (val.y - mean) * rstd * wv.y + bv.y;
        o4.z = (val.z - mean) * rstd * wv.z + bv.z;
        o4.w = (val.w - mean) * rstd * wv.w + bv.w;
        *(float4*)(dst + i) = o4;
    }
}

// ---------------- 2. 1x1-conv projection ------------------------------------
__global__ __launch_bounds__(128) void proj_kernel(
    const float* __restrict__ wq, const float* __restrict__ bq,
    const float* __restrict__ wk, const float* __restrict__ bk,
    const float* __restrict__ wv, const float* __restrict__ bv)
{
    int which = blockIdx.z;
    int n     = blockIdx.y;
    int p0    = blockIdx.x * 128;
    const float *src, *W, *B;
    float* dst;
    if (which == 0)      { src = g_qn; W = wq; B = bq; dst = g_q; }
    else if (which == 1) { src = g_kn; W = wk; B = bk; dst = g_k; }
    else                 { src = g_vn; W = wv; B = bv; dst = g_v; }

    __shared__ float Ws[C * C];
    __shared__ float Xs[C * 128];
    int tid = threadIdx.x;
    for (int i = tid; i < C * C; i += 128) Ws[i] = W[i];
    for (int c = 0; c < C; c++)
        Xs[c * 128 + tid] = src[n * CHW + c * HW + p0 + tid];
    __syncthreads();

    float xr[C];
#pragma unroll
    for (int c = 0; c < C; c++) xr[c] = Xs[c * 128 + tid];

    for (int o = 0; o < C; o++) {
        float acc = B[o];
        const float4* w4 = (const float4*)(Ws + o * C);
#pragma unroll
        for (int c4 = 0; c4 < C / 4; c4++) {
            float4 w = w4[c4];
            acc += w.x * xr[c4 * 4 + 0];
            acc += w.y * xr[c4 * 4 + 1];
            acc += w.z * xr[c4 * 4 + 2];
            acc += w.w * xr[c4 * 4 + 3];
        }
        dst[n * CHW + o * HW + p0 + tid] = acc;
    }
}

// ---------------- 3. fused attn = KtQ -> softmax(i) -> V@P + residual -------
// grid = (HW/JW, NB), block = 256
// dyn smem: P[1024*32] (128KB) | Kc[64*256]=Vt/redB (64KB) | Qs[64*32]=red (8KB)
__global__ __launch_bounds__(256) void fused_attn_kernel(
    float* __restrict__ attn_out, float* __restrict__ xout)
{
    extern __shared__ float smf[];
    float* P  = smf;                   // 32768 floats: logits/probs [i][j]
    float* Kc = smf + 32768;           // 16384 floats
    float* Qs = smf + 32768 + 16384;   // 2048 floats

    int n  = blockIdx.y;
    int j0 = blockIdx.x * JW;
    int tid = threadIdx.x;

    const float* kptr = g_k + n * CHW;
    const float* qptr = g_q + n * CHW;
    const float* vptr = g_v + n * CHW;

    // load Q stripe [64][32]
    for (int idx = tid; idx < C * JW; idx += 256) {
        int c = idx >> 5, j = idx & 31;
        Qs[idx] = qptr[c * HW + j0 + j];
    }
    __syncthreads();

    // ---- Pass A: logits = (1/8) K^T Q, 4 chunks of 256 i ----
    int igrp = tid >> 3;        // 0..31 -> 8 i's
    int jgrp = tid & 7;         // 0..7  -> 4 j's
    int ii0  = igrp * 8;
    int jj0  = jgrp * 4;

    for (int ic0 = 0; ic0 < HW; ic0 += 256) {
        // load K chunk [64][256]
        for (int idx4 = tid * 4; idx4 < C * 256; idx4 += 256 * 4) {
            int c = idx4 >> 8, ii = idx4 & 255;
            *(float4*)(Kc + c * 256 + ii) = *(const float4*)(kptr + c * HW + ic0 + ii);
        }
        __syncthreads();

        float acc[8][4];
#pragma unroll
        for (int a = 0; a < 8; a++)
#pragma unroll
            for (int b = 0; b < 4; b++) acc[a][b] = 0.f;

#pragma unroll 8
        for (int c = 0; c < C; c++) {
            float4 k0 = *(const float4*)(Kc + c * 256 + ii0);
            float4 k1 = *(const float4*)(Kc + c * 256 + ii0 + 4);
            float4 qv = *(const float4*)(Qs + c * JW + jj0);
            float kv[8] = {k0.x, k0.y, k0.z, k0.w, k1.x, k1.y, k1.z, k1.w};
            float qa[4] = {qv.x, qv.y, qv.z, qv.w};
#pragma unroll
            for (int a = 0; a < 8; a++)
#pragma unroll
                for (int b = 0; b < 4; b++)
                    acc[a][b] += kv[a] * qa[b];
        }
#pragma unroll
        for (int a = 0; a < 8; a++) {
            int i = ic0 + ii0 + a;
#pragma unroll
            for (int b = 0; b < 4; b++)
                P[i * JW + jj0 + b] = acc[a][b] * 0.125f;
        }
        __syncthreads();
    }

    // ---- softmax over i, per column j ----
    {
        int j   = tid & 31;
        int isl = tid >> 5;   // 0..7
        float* red = Qs;      // reuse

        float m = -CUDART_INF_F;
        for (int i = isl; i < HW; i += 8)
            m = fmaxf(m, P[i * JW + j]);
        red[isl * 32 + j] = m;
        __syncthreads();
        if (tid < 32) {
            float mm = red[tid];
#pragma unroll
            for (int s = 1; s < 8; s++) mm = fmaxf(mm, red[s * 32 + tid]);
            red[tid] = mm;
        }
        __syncthreads();
        m = red[j];
        __syncthreads();

        float s = 0.f;
        for (int i = isl; i < HW; i += 8) {
            float e = __expf(P[i * JW + j] - m);
            P[i * JW + j] = e;
            s += e;
        }
        red[256 + isl * 32 + j] = s;
        __syncthreads();
        if (tid < 32) {
            float ssum = red[256 + tid];
#pragma unroll
            for (int q2 = 1; q2 < 8; q2++) ssum += red[256 + q2 * 32 + tid];
            red[256 + tid] = ssum;
        }
        __syncthreads();
        float rs = 1.0f / red[256 + j];
        __syncthreads();

        float* aout = attn_out ? attn_out + (size_t)n * HW * HW + j0 : nullptr;
        for (int i = isl; i < HW; i += 8) {
            float p = P[i * JW + j] * rs;
            P[i * JW + j] = p;
            if (aout) aout[(size_t)i * HW + j] = p;
        }
        __syncthreads();
    }

    if (!xout) return;

    // ---- Pass B: out[c,j] = sum_i V[c,i] P[i,j]; x = qn + out ----
    // tid = isl2*64 + jg*8 + cg ; thread tile 8c x 4j, partial over i-slice
    int isl2 = tid >> 6;        // 0..3
    int rem  = tid & 63;
    int jg   = rem >> 3;        // 0..7 -> j = jg*4
    int cg   = rem & 7;         // 0..7 -> c = cg*8
    const int VT_STRIDE = 68;   // padded transpose stride (16B-aligned, low conflict)
    float* Vt = Kc;             // reuse (64*68 = 4352 floats)

    float acc2[8][4];
#pragma unroll
    for (int a = 0; a < 8; a++)
#pragma unroll
        for (int b = 0; b < 4; b++) acc2[a][b] = 0.f;

    for (int i0 = 0; i0 < HW; i0 += 64) {
        // transposed V tile: Vt[ii][c]
        for (int idx4 = tid * 4; idx4 < C * 64; idx4 += 256 * 4) {
            int c = idx4 >> 6, ii = idx4 & 63;
            float4 gv = *(const float4*)(vptr + c * HW + i0 + ii);
            Vt[(ii + 0) * VT_STRIDE + c] = gv.x;
            Vt[(ii + 1) * VT_STRIDE + c] = gv.y;
            Vt[(ii + 2) * VT_STRIDE + c] = gv.z;
            Vt[(ii + 3) * VT_STRIDE + c] = gv.w;
        }
        __syncthreads();

#pragma unroll 4
        for (int t = 0; t < 16; t++) {
            int il = isl2 * 16 + t;
            int i  = i0 + il;
            float4 p4 = *(const float4*)(P + i * JW + jg * 4);
            float4 v0 = *(const float4*)(Vt + il * VT_STRIDE + cg * 8);
            float4 v1 = *(const float4*)(Vt + il * VT_STRIDE + cg * 8 + 4);
            float vv[8] = {v0.x, v0.y, v0.z, v0.w, v1.x, v1.y, v1.z, v1.w};
            float pp[4] = {p4.x, p4.y, p4.z, p4.w};
#pragma unroll
            for (int a = 0; a < 8; a++)
#pragma unroll
                for (int b = 0; b < 4; b++)
                    acc2[a][b] += vv[a] * pp[b];
        }
        __syncthreads();
    }

    // reduce 4 i-slices via smem
    float* redB = Kc;  // 4 * 2048 floats
#pragma unroll
    for (int a = 0; a < 8; a++) {
        int c = cg * 8 + a;
        *(float4*)(redB + isl2 * 2048 + c * JW + jg * 4) =
            make_float4(acc2[a][0], acc2[a][1], acc2[a][2], acc2[a][3]);
    }
    __syncthreads();

    const float* qnptr = g_qn + n * CHW;
    for (int o = tid * 8; o < 2048; o += 256 * 8) {
#pragma unroll
        for (int u = 0; u < 8; u++) {
            int oi = o + u;
            int c = oi >> 5, j = oi & 31;
            float ssum = redB[oi] + redB[2048 + oi] + redB[4096 + oi] + redB[6144 + oi];
            xout[n * CHW + c * HW + j0 + j] = ssum + qnptr[c * HW + j0 + j];
        }
    }
}

// ---------------------------------------------------------------------------
extern "C" void kernel_launch(void* const* d_in, const int* in_sizes, int n_in,
                              void* d_out, int out_size)
{
    const float* query = (const float*)d_in[0];
    const float* key   = (const float*)d_in[1];
    const float* value = (const float*)d_in[2];
    const float* ln1w  = (const float*)d_in[3];
    const float* ln1b  = (const float*)d_in[4];
    const float* ln2w  = (const float*)d_in[5];
    const float* ln2b  = (const float*)d_in[6];
    const float* ln3w  = (const float*)d_in[7];
    const float* ln3b  = (const float*)d_in[8];
    const float* wq    = (const float*)d_in[9];
    const float* bq    = (const float*)d_in[10];
    const float* wk    = (const float*)d_in[11];
    const float* bk    = (const float*)d_in[12];
    const float* wv    = (const float*)d_in[13];
    const float* bv    = (const float*)d_in[14];

    float* out = (float*)d_out;
    const size_t XSZ = (size_t)NB * CHW;        // 2,097,152
    const size_t ASZ = (size_t)NB * HW * HW;    // 33,554,432

    float* x_out    = nullptr;
    float* attn_out = nullptr;
    size_t osz = (size_t)out_size;
    if (osz >= XSZ + ASZ)      { x_out = out; attn_out = out + XSZ; }
    else if (osz == ASZ)       { attn_out = out; }
    else                       { x_out = out; }

    static int smem_set = 0;
    const int FUSED_SMEM = (32768 + 16384 + 2048) * 4;   // 204800 B
    if (!smem_set) {
        cudaFuncSetAttribute(fused_attn_kernel,
                             cudaFuncAttributeMaxDynamicSharedMemorySize, FUSED_SMEM);
        smem_set = 1;
    }

    ln_kernel<<<NB * 3, 256>>>(query, key, value, ln1w, ln1b, ln2w, ln2b, ln3w, ln3b);
    proj_kernel<<<dim3(HW / 128, NB, 3), 128>>>(wq, bq, wk, bk, wv, bv);
    fused_attn_kernel<<<dim3(HW / JW, NB), 256, FUSED_SMEM>>>(attn_out, x_out);
}

// round 4
// speedup vs baseline: 2.0310x; 2.0310x over previous
#include <cuda_runtime.h>
#include <math_constants.h>

#define NB  32
#define C   64
#define HW  1024
#define CHW 65536
#define EPS 1e-5f

// ---------------- scratch (device globals; no allocations allowed) ----------
__device__ float g_qn[NB * CHW];
__device__ float g_kn[NB * CHW];
__device__ float g_vn[NB * CHW];
__device__ float g_q [NB * CHW];
__device__ float g_kt[NB * CHW];           // K transposed: [n][i][c]
__device__ float g_v [NB * CHW];
__device__ float g_attn[(size_t)NB * HW * HW];   // fallback logits buffer
__device__ float g_m [NB * HW];
__device__ float g_rs[NB * HW];

// ---------------- mma helpers ----------------------------------------------
__device__ __forceinline__ unsigned f2tf(float x) {
    unsigned u;
    asm("cvt.rna.tf32.f32 %0, %1;" : "=r"(u) : "f"(x));
    return u;
}

__device__ __forceinline__ void mma_tf32(float* d, const unsigned* a, const unsigned* b) {
    asm volatile(
        "mma.sync.aligned.m16n8k8.row.col.f32.tf32.tf32.f32 "
        "{%0,%1,%2,%3}, {%4,%5,%6,%7}, {%8,%9}, {%0,%1,%2,%3};\n"
        : "+f"(d[0]), "+f"(d[1]), "+f"(d[2]), "+f"(d[3])
        : "r"(a[0]), "r"(a[1]), "r"(a[2]), "r"(a[3]), "r"(b[0]), "r"(b[1]));
}

// ---------------- 1. LayerNorm over full (C,H,W) per sample ----------------
__global__ __launch_bounds__(1024) void ln_kernel(
    const float* __restrict__ q, const float* __restrict__ k, const float* __restrict__ v,
    const float* __restrict__ w1, const float* __restrict__ b1,
    const float* __restrict__ w2, const float* __restrict__ b2,
    const float* __restrict__ w3, const float* __restrict__ b3)
{
    int which = blockIdx.x % 3;
    int n     = blockIdx.x / 3;
    const float *x, *w, *b;
    float* dst;
    if (which == 0)      { x = q + n * CHW; w = w1; b = b1; dst = g_qn + n * CHW; }
    else if (which == 1) { x = k + n * CHW; w = w2; b = b2; dst = g_kn + n * CHW; }
    else                 { x = v + n * CHW; w = w3; b = b3; dst = g_vn + n * CHW; }

    int tid = threadIdx.x;
    float s = 0.f, ss = 0.f;
    for (int i = tid * 4; i < CHW; i += 1024 * 4) {
        float4 val = *(const float4*)(x + i);
        s  += val.x + val.y + val.z + val.w;
        ss += val.x * val.x + val.y * val.y + val.z * val.z + val.w * val.w;
    }
    __shared__ float sm[1024], sm2[1024];
    sm[tid] = s; sm2[tid] = ss;
    __syncthreads();
    for (int o = 512; o > 0; o >>= 1) {
        if (tid < o) { sm[tid] += sm[tid + o]; sm2[tid] += sm2[tid + o]; }
        __syncthreads();
    }
    float mean = sm[0] * (1.0f / CHW);
    float var  = sm2[0] * (1.0f / CHW) - mean * mean;
    float rstd = rsqrtf(var + EPS);

    for (int i = tid * 4; i < CHW; i += 1024 * 4) {
        float4 val = *(const float4*)(x + i);
        float4 wv  = *(const float4*)(w + i);
        float4 bv  = *(const float4*)(b + i);
        float4 o4;
        o4.x = (val.x - mean) * rstd * wv.x + bv.x;
        o4.y = (val.y - mean) * rstd * wv.y + bv.y;
        o4.z = (val.z - mean) * rstd * wv.z + bv.z;
        o4.w = (val.w - mean) * rstd * wv.w + bv.w;
        *(float4*)(dst + i) = o4;
    }
}

// ---------------- 2. projection; K output transposed to [i][c] -------------
__global__ __launch_bounds__(128) void proj_kernel(
    const float* __restrict__ wq, const float* __restrict__ bq,
    const float* __restrict__ wk, const float* __restrict__ bk,
    const float* __restrict__ wv, const float* __restrict__ bv)
{
    int which = blockIdx.z;
    int n     = blockIdx.y;
    int p0    = blockIdx.x * 128;
    const float *src, *W, *B;
    if (which == 0)      { src = g_qn; W = wq; B = bq; }
    else if (which == 1) { src = g_kn; W = wk; B = bk; }
    else                 { src = g_vn; W = wv; B = bv; }

    __shared__ float smp[12288];          // 48 KB: Ws[4096] | Xs[8192]
    float* Ws = smp;
    float* Xs = smp + 4096;
    int tid = threadIdx.x;
    for (int i = tid; i < C * C; i += 128) Ws[i] = W[i];
    for (int c = 0; c < C; c++)
        Xs[c * 128 + tid] = src[n * CHW + c * HW + p0 + tid];
    __syncthreads();

    float xr[C];
#pragma unroll
    for (int c = 0; c < C; c++) xr[c] = Xs[c * 128 + tid];

    float accv[C];
    for (int o = 0; o < C; o++) {
        float acc = B[o];
        const float4* w4 = (const float4*)(Ws + o * C);
#pragma unroll
        for (int c4 = 0; c4 < C / 4; c4++) {
            float4 w = w4[c4];
            acc += w.x * xr[c4 * 4 + 0];
            acc += w.y * xr[c4 * 4 + 1];
            acc += w.z * xr[c4 * 4 + 2];
            acc += w.w * xr[c4 * 4 + 3];
        }
        accv[o] = acc;
    }

    if (which != 1) {
        float* dst = (which == 0 ? g_q : g_v) + n * CHW;
        for (int o = 0; o < C; o++)
            dst[o * HW + p0 + tid] = accv[o];
    } else {
        // transpose to g_kt[n][i][c] via smem staging (stride 65: conflict-free)
        __syncthreads();
        float* T = smp;  // [128][65] = 8320 <= 12288
#pragma unroll
        for (int o = 0; o < C; o++) T[tid * 65 + o] = accv[o];
        __syncthreads();
        float* dst = g_kt + n * CHW;
        for (int idx = tid; idx < 128 * 16; idx += 128) {
            int p = idx >> 4, c4 = (idx & 15) << 2;
            float4 v = make_float4(T[p * 65 + c4], T[p * 65 + c4 + 1],
                                   T[p * 65 + c4 + 2], T[p * 65 + c4 + 3]);
            *(float4*)(dst + (p0 + p) * C + c4) = v;
        }
    }
}

// ---------------- 3. logits = (1/8) K^T Q via tf32 mma ---------------------
// grid = (8 jt, 8 it, 32 n), block 256; tile 128x128, K-dim = C = 64
#define AS_STR 68
#define BS_STR 136
__global__ __launch_bounds__(256) void logits_kernel(float* __restrict__ logits_ext)
{
    extern __shared__ unsigned sm_u[];
    unsigned* As = sm_u;                   // [128][68] Kt tile (i rows, c cols)
    unsigned* Bs = sm_u + 128 * AS_STR;    // [64][136] Q tile  (c rows, j cols)

    int n = blockIdx.z, i0 = blockIdx.y * 128, j0 = blockIdx.x * 128;
    int tid = threadIdx.x;
    const float* kt = g_kt + (size_t)n * CHW;
    const float* qp = g_q  + (size_t)n * CHW;
    float* L = logits_ext ? logits_ext : g_attn;

    for (int idx = tid; idx < 128 * 16; idx += 256) {
        int i = idx >> 4, c4 = (idx & 15) << 2;
        float4 v = *(const float4*)(kt + (size_t)(i0 + i) * C + c4);
        *(uint4*)(As + i * AS_STR + c4) =
            make_uint4(f2tf(v.x), f2tf(v.y), f2tf(v.z), f2tf(v.w));
    }
    for (int idx = tid; idx < 64 * 32; idx += 256) {
        int c = idx >> 5, j4 = (idx & 31) << 2;
        float4 v = *(const float4*)(qp + c * HW + j0 + j4);
        *(uint4*)(Bs + c * BS_STR + j4) =
            make_uint4(f2tf(v.x), f2tf(v.y), f2tf(v.z), f2tf(v.w));
    }
    __syncthreads();

    int wid = tid >> 5, lane = tid & 31;
    int g = lane >> 2, tig = lane & 3;
    int wm = (wid & 1) * 64;
    int wn = (wid >> 1) * 32;

    float acc[4][4][4] = {};
#pragma unroll
    for (int kk = 0; kk < 8; kk++) {
        int c0 = kk * 8;
        unsigned a[4][4], b[4][2];
#pragma unroll
        for (int mf = 0; mf < 4; mf++) {
            int r = wm + mf * 16 + g;
            a[mf][0] = As[r * AS_STR + c0 + tig];
            a[mf][1] = As[(r + 8) * AS_STR + c0 + tig];
            a[mf][2] = As[r * AS_STR + c0 + tig + 4];
            a[mf][3] = As[(r + 8) * AS_STR + c0 + tig + 4];
        }
#pragma unroll
        for (int nf = 0; nf < 4; nf++) {
            int col = wn + nf * 8 + g;
            b[nf][0] = Bs[(c0 + tig) * BS_STR + col];
            b[nf][1] = Bs[(c0 + tig + 4) * BS_STR + col];
        }
#pragma unroll
        for (int mf = 0; mf < 4; mf++)
#pragma unroll
            for (int nf = 0; nf < 4; nf++)
                mma_tf32(acc[mf][nf], a[mf], b[nf]);
    }

    float* out = L + (size_t)n * HW * HW;
#pragma unroll
    for (int mf = 0; mf < 4; mf++) {
        int ib = i0 + wm + mf * 16 + g;
#pragma unroll
        for (int nf = 0; nf < 4; nf++) {
            int j = j0 + wn + nf * 8 + 2 * tig;
            *(float2*)(out + (size_t)ib * HW + j) =
                make_float2(acc[mf][nf][0] * 0.125f, acc[mf][nf][1] * 0.125f);
            *(float2*)(out + (size_t)(ib + 8) * HW + j) =
                make_float2(acc[mf][nf][2] * 0.125f, acc[mf][nf][3] * 0.125f);
        }
    }
}

// ---------------- 4. per-column online max / sum-exp ------------------------
// grid = (8, 32), block 256 (2 i-slices x 128 j)
__global__ __launch_bounds__(256) void colstats_kernel(const float* __restrict__ logits_ext)
{
    const float* L = logits_ext ? logits_ext : g_attn;
    int n = blockIdx.y;
    int j = blockIdx.x * 128 + (threadIdx.x & 127);
    int isl = threadIdx.x >> 7;
    const float* base = L + (size_t)n * HW * HW + j;

    float m = -CUDART_INF_F, s = 0.f;
    for (int ib = isl * 8; ib < HW; ib += 16) {
        float v[8];
#pragma unroll
        for (int r = 0; r < 8; r++) v[r] = base[(size_t)(ib + r) * HW];
        float cm = v[0];
#pragma unroll
        for (int r = 1; r < 8; r++) cm = fmaxf(cm, v[r]);
        float mn = fmaxf(m, cm);
        float acc = s * __expf(m - mn);
#pragma unroll
        for (int r = 0; r < 8; r++) acc += __expf(v[r] - mn);
        s = acc; m = mn;
    }
    __shared__ float shm[256], shs[256];
    shm[threadIdx.x] = m; shs[threadIdx.x] = s;
    __syncthreads();
    if (isl == 0) {
        float m1 = shm[threadIdx.x + 128], s1 = shs[threadIdx.x + 128];
        float M = fmaxf(m, m1);
        float S = s * __expf(m - M) + s1 * __expf(m1 - M);
        g_m [n * HW + j] = M;
        g_rs[n * HW + j] = 1.0f / S;
    }
}

// ---------------- 5. out = V @ softmax(logits) + qn; write probs ------------
// grid = (8 jt, 32 n), block 256; M=64(c) N=128(j) K=1024(i) chunked by 64
__global__ __launch_bounds__(256) void out_kernel(
    const float* __restrict__ logits_ext,
    float* __restrict__ attn_out, float* __restrict__ xout)
{
    extern __shared__ unsigned sm_u[];
    unsigned* As = sm_u;                 // V [64 c][72] (i cols)
    unsigned* Bs = sm_u + 64 * 72;       // P [64 i][136] (j cols)
    float* mcol = (float*)(sm_u + 64 * 72 + 64 * 136);
    float* rcol = mcol + 128;

    int n = blockIdx.y, j0 = blockIdx.x * 128;
    int tid = threadIdx.x;
    const float* vp = g_v + (size_t)n * CHW;
    const float* lg = (logits_ext ? logits_ext : g_attn) + (size_t)n * HW * HW;
    float* ap = attn_out ? attn_out + (size_t)n * HW * HW : nullptr;

    if (tid < 128) {
        mcol[tid] = g_m [n * HW + j0 + tid];
        rcol[tid] = g_rs[n * HW + j0 + tid];
    }
    __syncthreads();

    int wid = tid >> 5, lane = tid & 31;
    int g = lane >> 2, tig = lane & 3;
    int wm = (wid & 1) * 32;    // c offset
    int wn = (wid >> 1) * 32;   // j offset
    float acc[2][4][4] = {};

    for (int ic0 = 0; ic0 < HW; ic0 += 64) {
        for (int idx = tid; idx < 64 * 16; idx += 256) {
            int c = idx >> 4, i4 = (idx & 15) << 2;
            float4 v = *(const float4*)(vp + c * HW + ic0 + i4);
            *(uint4*)(As + c * 72 + i4) =
                make_uint4(f2tf(v.x), f2tf(v.y), f2tf(v.z), f2tf(v.w));
        }
        for (int idx = tid; idx < 64 * 32; idx += 256) {
            int ii = idx >> 5, j4 = (idx & 31) << 2;
            float4 l4 = *(const float4*)(lg + (size_t)(ic0 + ii) * HW + j0 + j4);
            float4 m4 = *(const float4*)(mcol + j4);
            float4 r4 = *(const float4*)(rcol + j4);
            float4 p4;
            p4.x = __expf(l4.x - m4.x) * r4.x;
            p4.y = __expf(l4.y - m4.y) * r4.y;
            p4.z = __expf(l4.z - m4.z) * r4.z;
            p4.w = __expf(l4.w - m4.w) * r4.w;
            if (ap) *(float4*)(ap + (size_t)(ic0 + ii) * HW + j0 + j4) = p4;
            *(uint4*)(Bs + ii * 136 + j4) =
                make_uint4(f2tf(p4.x), f2tf(p4.y), f2tf(p4.z), f2tf(p4.w));
        }
        __syncthreads();
#pragma unroll
        for (int kk = 0; kk < 8; kk++) {
            int k0 = kk * 8;
            unsigned a[2][4], b[4][2];
#pragma unroll
            for (int mf = 0; mf < 2; mf++) {
                int r = wm + mf * 16 + g;
                a[mf][0] = As[r * 72 + k0 + tig];
                a[mf][1] = As[(r + 8) * 72 + k0 + tig];
                a[mf][2] = As[r * 72 + k0 + tig + 4];
                a[mf][3] = As[(r + 8) * 72 + k0 + tig + 4];
            }
#pragma unroll
            for (int nf = 0; nf < 4; nf++) {
                int col = wn + nf * 8 + g;
                b[nf][0] = Bs[(k0 + tig) * 136 + col];
                b[nf][1] = Bs[(k0 + tig + 4) * 136 + col];
            }
#pragma unroll
            for (int mf = 0; mf < 2; mf++)
#pragma unroll
                for (int nf = 0; nf < 4; nf++)
                    mma_tf32(acc[mf][nf], a[mf], b[nf]);
        }
        __syncthreads();
    }

    if (!xout) return;
    const float* qn = g_qn + (size_t)n * CHW;
    float* xp = xout + (size_t)n * CHW;
#pragma unroll
    for (int mf = 0; mf < 2; mf++) {
        int c = wm + mf * 16 + g;
#pragma unroll
        for (int nf = 0; nf < 4; nf++) {
            int j = j0 + wn + nf * 8 + 2 * tig;
            float2 q0 = *(const float2*)(qn + c * HW + j);
            float2 q1 = *(const float2*)(qn + (c + 8) * HW + j);
            *(float2*)(xp + c * HW + j) =
                make_float2(acc[mf][nf][0] + q0.x, acc[mf][nf][1] + q0.y);
            *(float2*)(xp + (c + 8) * HW + j) =
                make_float2(acc[mf][nf][2] + q1.x, acc[mf][nf][3] + q1.y);
        }
    }
}

// ---------------------------------------------------------------------------
extern "C" void kernel_launch(void* const* d_in, const int* in_sizes, int n_in,
                              void* d_out, int out_size)
{
    const float* query = (const float*)d_in[0];
    const float* key   = (const float*)d_in[1];
    const float* value = (const float*)d_in[2];
    const float* ln1w  = (const float*)d_in[3];
    const float* ln1b  = (const float*)d_in[4];
    const float* ln2w  = (const float*)d_in[5];
    const float* ln2b  = (const float*)d_in[6];
    const float* ln3w  = (const float*)d_in[7];
    const float* ln3b  = (const float*)d_in[8];
    const float* wq    = (const float*)d_in[9];
    const float* bq    = (const float*)d_in[10];
    const float* wk    = (const float*)d_in[11];
    const float* bk    = (const float*)d_in[12];
    const float* wv    = (const float*)d_in[13];
    const float* bv    = (const float*)d_in[14];

    float* out = (float*)d_out;
    const size_t XSZ = (size_t)NB * CHW;
    const size_t ASZ = (size_t)NB * HW * HW;

    float* x_out    = nullptr;
    float* attn_out = nullptr;
    size_t osz = (size_t)out_size;
    if (osz >= XSZ + ASZ)      { x_out = out; attn_out = out + XSZ; }
    else if (osz == ASZ)       { attn_out = out; }
    else                       { x_out = out; }

    static int attr_set = 0;
    const int LOGITS_SMEM = (128 * AS_STR + 64 * BS_STR) * 4;       // 69632
    const int OUT_SMEM    = (64 * 72 + 64 * 136 + 256) * 4;         // 54272
    if (!attr_set) {
        cudaFuncSetAttribute(logits_kernel,
                             cudaFuncAttributeMaxDynamicSharedMemorySize, LOGITS_SMEM);
        cudaFuncSetAttribute(out_kernel,
                             cudaFuncAttributeMaxDynamicSharedMemorySize, OUT_SMEM);
        attr_set = 1;
    }

    ln_kernel<<<NB * 3, 1024>>>(query, key, value, ln1w, ln1b, ln2w, ln2b, ln3w, ln3b);
    proj_kernel<<<dim3(HW / 128, NB, 3), 128>>>(wq, bq, wk, bk, wv, bv);
    logits_kernel<<<dim3(8, 8, NB), 256, LOGITS_SMEM>>>(attn_out);
    colstats_kernel<<<dim3(8, NB), 256>>>(attn_out);
    out_kernel<<<dim3(8, NB), 256, OUT_SMEM>>>(attn_out, attn_out, x_out);
}

// round 6
// speedup vs baseline: 2.1022x; 1.0350x over previous
#include <cuda_runtime.h>
#include <math_constants.h>

#define NB  32
#define C   64
#define HW  1024
#define CHW 65536
#define EPS 1e-5f
#define JT  64      // j-stripe per flash block
#define IC  64      // i-chunk
#define LSCALE 0.180336880f   // 0.125 * log2(e)

// ---------------- scratch (device globals; no allocations allowed) ----------
__device__ float g_qn[NB * CHW];
__device__ float g_kn[NB * CHW];
__device__ float g_vn[NB * CHW];
__device__ float g_q [NB * CHW];
__device__ float g_kt[NB * CHW];           // K transposed: [n][i][c]
__device__ float g_v [NB * CHW];

// ---------------- helpers ---------------------------------------------------
__device__ __forceinline__ unsigned f2tf(float x) {
    unsigned u;
    asm("cvt.rna.tf32.f32 %0, %1;" : "=r"(u) : "f"(x));
    return u;
}
__device__ __forceinline__ float ex2(float x) {
    float y;
    asm("ex2.approx.f32 %0, %1;" : "=f"(y) : "f"(x));
    return y;
}
__device__ __forceinline__ void mma_tf32(float* d, const unsigned* a, const unsigned* b) {
    asm volatile(
        "mma.sync.aligned.m16n8k8.row.col.f32.tf32.tf32.f32 "
        "{%0,%1,%2,%3}, {%4,%5,%6,%7}, {%8,%9}, {%0,%1,%2,%3};\n"
        : "+f"(d[0]), "+f"(d[1]), "+f"(d[2]), "+f"(d[3])
        : "r"(a[0]), "r"(a[1]), "r"(a[2]), "r"(a[3]), "r"(b[0]), "r"(b[1]));
}

// ---------------- 1. LayerNorm over full (C,H,W) per sample ----------------
__global__ __launch_bounds__(1024) void ln_kernel(
    const float* __restrict__ q, const float* __restrict__ k, const float* __restrict__ v,
    const float* __restrict__ w1, const float* __restrict__ b1,
    const float* __restrict__ w2, const float* __restrict__ b2,
    const float* __restrict__ w3, const float* __restrict__ b3)
{
    int which = blockIdx.x % 3;
    int n     = blockIdx.x / 3;
    const float *x, *w, *b;
    float* dst;
    if (which == 0)      { x = q + n * CHW; w = w1; b = b1; dst = g_qn + n * CHW; }
    else if (which == 1) { x = k + n * CHW; w = w2; b = b2; dst = g_kn + n * CHW; }
    else                 { x = v + n * CHW; w = w3; b = b3; dst = g_vn + n * CHW; }

    int tid = threadIdx.x;
    float s = 0.f, ss = 0.f;
    for (int i = tid * 4; i < CHW; i += 1024 * 4) {
        float4 val = *(const float4*)(x + i);
        s  += val.x + val.y + val.z + val.w;
        ss += val.x * val.x + val.y * val.y + val.z * val.z + val.w * val.w;
    }
    __shared__ float sm[1024], sm2[1024];
    sm[tid] = s; sm2[tid] = ss;
    __syncthreads();
    for (int o = 512; o > 0; o >>= 1) {
        if (tid < o) { sm[tid] += sm[tid + o]; sm2[tid] += sm2[tid + o]; }
        __syncthreads();
    }
    float mean = sm[0] * (1.0f / CHW);
    float var  = sm2[0] * (1.0f / CHW) - mean * mean;
    float rstd = rsqrtf(var + EPS);

    for (int i = tid * 4; i < CHW; i += 1024 * 4) {
        float4 val = *(const float4*)(x + i);
        float4 wv  = *(const float4*)(w + i);
        float4 bv  = *(const float4*)(b + i);
        float4 o4;
        o4.x = (val.x - mean) * rstd * wv.x + bv.x;
        o4.y = (val.y - mean) * rstd * wv.y + bv.y;
        o4.z = (val.z - mean) * rstd * wv.z + bv.z;
        o4.w = (val.w - mean) * rstd * wv.w + bv.w;
        *(float4*)(dst + i) = o4;
    }
}

// ---------------- 2. projection via tf32 mma; K transposed ------------------
// grid = (4 pt, NB, 3), block 256. Tile M=64(o) N=256(p) K=64(c)
// dyn smem (u32): Ws[64*68]=4352 | Xs[64*264]=16896 ; T reuses from 4352 and
// needs 256*68=17408 -> total budget 4352+17408 = 21760 u32 = 87040 B
__global__ __launch_bounds__(256) void proj_kernel(
    const float* __restrict__ wq, const float* __restrict__ bq,
    const float* __restrict__ wk, const float* __restrict__ bk,
    const float* __restrict__ wv, const float* __restrict__ bv)
{
    extern __shared__ unsigned psm[];
    unsigned* Ws = psm;              // [64 o][68]
    unsigned* Xs = psm + 64 * 68;    // [64 c][264]

    int which = blockIdx.z;
    int n     = blockIdx.y;
    int p0    = blockIdx.x * 256;
    const float *src, *W, *B;
    if (which == 0)      { src = g_qn; W = wq; B = bq; }
    else if (which == 1) { src = g_kn; W = wk; B = bk; }
    else                 { src = g_vn; W = wv; B = bv; }
    src += (size_t)n * CHW;

    int tid = threadIdx.x;
    for (int idx = tid; idx < 64 * 16; idx += 256) {
        int o = idx >> 4, c4 = (idx & 15) << 2;
        float4 v = *(const float4*)(W + o * C + c4);
        *(uint4*)(Ws + o * 68 + c4) =
            make_uint4(f2tf(v.x), f2tf(v.y), f2tf(v.z), f2tf(v.w));
    }
    for (int idx = tid; idx < 64 * 64; idx += 256) {
        int c = idx >> 6, p4 = (idx & 63) << 2;
        float4 v = *(const float4*)(src + c * HW + p0 + p4);
        *(uint4*)(Xs + c * 264 + p4) =
            make_uint4(f2tf(v.x), f2tf(v.y), f2tf(v.z), f2tf(v.w));
    }
    __syncthreads();

    int wid = tid >> 5, lane = tid & 31;
    int g = lane >> 2, tig = lane & 3;
    int wn = wid * 32;

    float acc[4][4][4] = {};
#pragma unroll
    for (int kk = 0; kk < 8; kk++) {
        int c0 = kk * 8;
        unsigned a[4][4], b[4][2];
#pragma unroll
        for (int mf = 0; mf < 4; mf++) {
            int r = mf * 16 + g;
            a[mf][0] = Ws[r * 68 + c0 + tig];
            a[mf][1] = Ws[(r + 8) * 68 + c0 + tig];
            a[mf][2] = Ws[r * 68 + c0 + tig + 4];
            a[mf][3] = Ws[(r + 8) * 68 + c0 + tig + 4];
        }
#pragma unroll
        for (int nf = 0; nf < 4; nf++) {
            int col = wn + nf * 8 + g;
            b[nf][0] = Xs[(c0 + tig) * 264 + col];
            b[nf][1] = Xs[(c0 + tig + 4) * 264 + col];
        }
#pragma unroll
        for (int mf = 0; mf < 4; mf++)
#pragma unroll
            for (int nf = 0; nf < 4; nf++)
                mma_tf32(acc[mf][nf], a[mf], b[nf]);
    }

    if (which != 1) {
        float* dst = (which == 0 ? g_q : g_v) + (size_t)n * CHW;
#pragma unroll
        for (int mf = 0; mf < 4; mf++) {
            int o = mf * 16 + g;
            float b0 = B[o], b1 = B[o + 8];
#pragma unroll
            for (int nf = 0; nf < 4; nf++) {
                int p = p0 + wn + nf * 8 + 2 * tig;
                *(float2*)(dst + o * HW + p) =
                    make_float2(acc[mf][nf][0] + b0, acc[mf][nf][1] + b0);
                *(float2*)(dst + (o + 8) * HW + p) =
                    make_float2(acc[mf][nf][2] + b1, acc[mf][nf][3] + b1);
            }
        }
    } else {
        // stage transpose: T[p][o], stride 68, 256 rows (fits: see smem comment)
        __syncthreads();
        float* T = (float*)Xs;
#pragma unroll
        for (int mf = 0; mf < 4; mf++) {
            int o = mf * 16 + g;
            float b0 = B[o], b1 = B[o + 8];
#pragma unroll
            for (int nf = 0; nf < 4; nf++) {
                int p = wn + nf * 8 + 2 * tig;
                T[p * 68 + o]           = acc[mf][nf][0] + b0;
                T[(p + 1) * 68 + o]     = acc[mf][nf][1] + b0;
                T[p * 68 + o + 8]       = acc[mf][nf][2] + b1;
                T[(p + 1) * 68 + o + 8] = acc[mf][nf][3] + b1;
            }
        }
        __syncthreads();
        float* dst = g_kt + (size_t)n * CHW;
        for (int idx = tid; idx < 256 * 16; idx += 256) {
            int p = idx >> 4, c4 = (idx & 15) << 2;
            float4 v = make_float4(T[p * 68 + c4], T[p * 68 + c4 + 1],
                                   T[p * 68 + c4 + 2], T[p * 68 + c4 + 3]);
            *(float4*)(dst + (size_t)(p0 + p) * C + c4) = v;
        }
    }
}

// ---------------- 3. flash: stats pass + recompute/output pass --------------
// grid = (16 jt, NB), block 256 (8 warps)
// smem (u32): Qs[64][72] | As[64][68] | Vs[64][72] | Ps[64][72] | m[64]|rs[64]
__global__ __launch_bounds__(256) void flash_kernel(
    float* __restrict__ attn_out, float* __restrict__ xout)
{
    extern __shared__ unsigned fsm[];
    unsigned* Qs = fsm;                         // 4608
    unsigned* As = fsm + 4608;                  // 4352
    unsigned* Vs = fsm + 4608 + 4352;           // 4608
    unsigned* Ps = fsm + 4608 + 4352 + 4608;    // 4608
    float*    Psf  = (float*)Ps;
    float*    mcol = (float*)(fsm + 18176);
    float*    rcol = mcol + 64;

    int n  = blockIdx.y;
    int j0 = blockIdx.x * JT;
    int tid = threadIdx.x;
    const float* kt = g_kt + (size_t)n * CHW;
    const float* qp = g_q  + (size_t)n * CHW;
    const float* vp = g_v  + (size_t)n * CHW;

    // Q stripe, pre-scaled by 0.125*log2(e)
    for (int idx = tid; idx < 64 * 16; idx += 256) {
        int c = idx >> 4, j4 = (idx & 15) << 2;
        float4 v = *(const float4*)(qp + c * HW + j0 + j4);
        *(uint4*)(Qs + c * 72 + j4) =
            make_uint4(f2tf(v.x * LSCALE), f2tf(v.y * LSCALE),
                       f2tf(v.z * LSCALE), f2tf(v.w * LSCALE));
    }

    int wid = tid >> 5, lane = tid & 31;
    int g = lane >> 2, tig = lane & 3;
    int wm = (wid & 1) * 32;         // i (mma1) or c (mma2)
    int wn = (wid >> 1) * 16;        // j

    // -------- Phase A: column stats via online (m, sumexp2) --------
    int jcol = tid & 63;
    int qd   = tid >> 6;             // 0..3 : rows qd*16..+16 of each chunk
    float m_run = -CUDART_INF_F, s_run = 0.f;

    for (int ch = 0; ch < 16; ch++) {
        int i0 = ch * IC;
        __syncthreads();
        for (int idx = tid; idx < 64 * 16; idx += 256) {
            int i = idx >> 4, c4 = (idx & 15) << 2;
            float4 v = *(const float4*)(kt + (size_t)(i0 + i) * C + c4);
            *(uint4*)(As + i * 68 + c4) =
                make_uint4(f2tf(v.x), f2tf(v.y), f2tf(v.z), f2tf(v.w));
        }
        __syncthreads();

        float acc1[2][2][4] = {};
#pragma unroll
        for (int kk = 0; kk < 8; kk++) {
            int c0 = kk * 8;
            unsigned a[2][4], b[2][2];
#pragma unroll
            for (int mf = 0; mf < 2; mf++) {
                int r = wm + mf * 16 + g;
                a[mf][0] = As[r * 68 + c0 + tig];
                a[mf][1] = As[(r + 8) * 68 + c0 + tig];
                a[mf][2] = As[r * 68 + c0 + tig + 4];
                a[mf][3] = As[(r + 8) * 68 + c0 + tig + 4];
            }
#pragma unroll
            for (int nf = 0; nf < 2; nf++) {
                int col = wn + nf * 8 + g;
                b[nf][0] = Qs[(c0 + tig) * 72 + col];
                b[nf][1] = Qs[(c0 + tig + 4) * 72 + col];
            }
#pragma unroll
            for (int mf = 0; mf < 2; mf++)
#pragma unroll
                for (int nf = 0; nf < 2; nf++)
                    mma_tf32(acc1[mf][nf], a[mf], b[nf]);
        }
#pragma unroll
        for (int mf = 0; mf < 2; mf++) {
            int r = wm + mf * 16 + g;
#pragma unroll
            for (int nf = 0; nf < 2; nf++) {
                int col = wn + nf * 8 + 2 * tig;
                *(float2*)(Psf + r * 72 + col)       = make_float2(acc1[mf][nf][0], acc1[mf][nf][1]);
                *(float2*)(Psf + (r + 8) * 72 + col) = make_float2(acc1[mf][nf][2], acc1[mf][nf][3]);
            }
        }
        __syncthreads();

        float cmax = -CUDART_INF_F;
#pragma unroll
        for (int r = 0; r < 16; r++)
            cmax = fmaxf(cmax, Psf[(qd * 16 + r) * 72 + jcol]);
        float mn = fmaxf(m_run, cmax);
        float acc = s_run * ex2(m_run - mn);
#pragma unroll
        for (int r = 0; r < 16; r++)
            acc += ex2(Psf[(qd * 16 + r) * 72 + jcol] - mn);
        s_run = acc; m_run = mn;
    }
    __syncthreads();
    Psf[qd * 64 + jcol]       = m_run;
    Psf[256 + qd * 64 + jcol] = s_run;
    __syncthreads();
    if (tid < 64) {
        float M = Psf[tid];
#pragma unroll
        for (int q2 = 1; q2 < 4; q2++) M = fmaxf(M, Psf[q2 * 64 + tid]);
        float S = 0.f;
#pragma unroll
        for (int q2 = 0; q2 < 4; q2++)
            S += Psf[256 + q2 * 64 + tid] * ex2(Psf[q2 * 64 + tid] - M);
        mcol[tid] = M;
        rcol[tid] = 1.0f / S;
    }
    __syncthreads();

    // per-thread column stats (4 columns: nf x parity)
    float mj[2][2], rj[2][2];
#pragma unroll
    for (int nf = 0; nf < 2; nf++)
#pragma unroll
        for (int par = 0; par < 2; par++) {
            int col = wn + nf * 8 + 2 * tig + par;
            mj[nf][par] = mcol[col];
            rj[nf][par] = rcol[col];
        }

    // -------- Phase B: recompute logits, emit probs, V@P, residual ----------
    float* ap = attn_out ? attn_out + (size_t)n * HW * HW + j0 : nullptr;
    float acc2[2][2][4] = {};

    for (int ch = 0; ch < 16; ch++) {
        int i0 = ch * IC;
        __syncthreads();
        for (int idx = tid; idx < 64 * 16; idx += 256) {
            int i = idx >> 4, c4 = (idx & 15) << 2;
            float4 v = *(const float4*)(kt + (size_t)(i0 + i) * C + c4);
            *(uint4*)(As + i * 68 + c4) =
                make_uint4(f2tf(v.x), f2tf(v.y), f2tf(v.z), f2tf(v.w));
        }
        for (int idx = tid; idx < 64 * 16; idx += 256) {
            int c = idx >> 4, i4 = (idx & 15) << 2;
            float4 v = *(const float4*)(vp + c * HW + i0 + i4);
            *(uint4*)(Vs + c * 72 + i4) =
                make_uint4(f2tf(v.x), f2tf(v.y), f2tf(v.z), f2tf(v.w));
        }
        __syncthreads();

        float acc1[2][2][4] = {};
#pragma unroll
        for (int kk = 0; kk < 8; kk++) {
            int c0 = kk * 8;
            unsigned a[2][4], b[2][2];
#pragma unroll
            for (int mf = 0; mf < 2; mf++) {
                int r = wm + mf * 16 + g;
                a[mf][0] = As[r * 68 + c0 + tig];
                a[mf][1] = As[(r + 8) * 68 + c0 + tig];
                a[mf][2] = As[r * 68 + c0 + tig + 4];
                a[mf][3] = As[(r + 8) * 68 + c0 + tig + 4];
            }
#pragma unroll
            for (int nf = 0; nf < 2; nf++) {
                int col = wn + nf * 8 + g;
                b[nf][0] = Qs[(c0 + tig) * 72 + col];
                b[nf][1] = Qs[(c0 + tig + 4) * 72 + col];
            }
#pragma unroll
            for (int mf = 0; mf < 2; mf++)
#pragma unroll
                for (int nf = 0; nf < 2; nf++)
                    mma_tf32(acc1[mf][nf], a[mf], b[nf]);
        }

        // probs: exp2(logit - m) * (1/S); write global + smem(tf32)
#pragma unroll
        for (int mf = 0; mf < 2; mf++) {
            int il = wm + mf * 16 + g;
#pragma unroll
            for (int nf = 0; nf < 2; nf++) {
                int col = wn + nf * 8 + 2 * tig;
                float p0 = ex2(acc1[mf][nf][0] - mj[nf][0]) * rj[nf][0];
                float p1 = ex2(acc1[mf][nf][1] - mj[nf][1]) * rj[nf][1];
                float p2 = ex2(acc1[mf][nf][2] - mj[nf][0]) * rj[nf][0];
                float p3 = ex2(acc1[mf][nf][3] - mj[nf][1]) * rj[nf][1];
                if (ap) {
                    *(float2*)(ap + (size_t)(i0 + il) * HW + col)     = make_float2(p0, p1);
                    *(float2*)(ap + (size_t)(i0 + il + 8) * HW + col) = make_float2(p2, p3);
                }
                *(uint2*)(Ps + il * 72 + col)       = make_uint2(f2tf(p0), f2tf(p1));
                *(uint2*)(Ps + (il + 8) * 72 + col) = make_uint2(f2tf(p2), f2tf(p3));
            }
        }
        __syncthreads();

        if (xout) {
#pragma unroll
            for (int kk = 0; kk < 8; kk++) {
                int k0 = kk * 8;
                unsigned a[2][4], b[2][2];
#pragma unroll
                for (int mf = 0; mf < 2; mf++) {
                    int r = wm + mf * 16 + g;     // c row
                    a[mf][0] = Vs[r * 72 + k0 + tig];
                    a[mf][1] = Vs[(r + 8) * 72 + k0 + tig];
                    a[mf][2] = Vs[r * 72 + k0 + tig + 4];
                    a[mf][3] = Vs[(r + 8) * 72 + k0 + tig + 4];
                }
#pragma unroll
                for (int nf = 0; nf < 2; nf++) {
                    int col = wn + nf * 8 + g;
                    b[nf][0] = Ps[(k0 + tig) * 72 + col];
                    b[nf][1] = Ps[(k0 + tig + 4) * 72 + col];
                }
#pragma unroll
                for (int mf = 0; mf < 2; mf++)
#pragma unroll
                    for (int nf = 0; nf < 2; nf++)
                        mma_tf32(acc2[mf][nf], a[mf], b[nf]);
            }
        }
    }

    if (!xout) return;
    const float* qn = g_qn + (size_t)n * CHW;
    float* xp = xout + (size_t)n * CHW;
#pragma unroll
    for (int mf = 0; mf < 2; mf++) {
        int c = wm + mf * 16 + g;
#pragma unroll
        for (int nf = 0; nf < 2; nf++) {
            int j = j0 + wn + nf * 8 + 2 * tig;
            float2 q0 = *(const float2*)(qn + c * HW + j);
            float2 q1 = *(const float2*)(qn + (c + 8) * HW + j);
            *(float2*)(xp + c * HW + j) =
                make_float2(acc2[mf][nf][0] + q0.x, acc2[mf][nf][1] + q0.y);
            *(float2*)(xp + (c + 8) * HW + j) =
                make_float2(acc2[mf][nf][2] + q1.x, acc2[mf][nf][3] + q1.y);
        }
    }
}

// ---------------------------------------------------------------------------
extern "C" void kernel_launch(void* const* d_in, const int* in_sizes, int n_in,
                              void* d_out, int out_size)
{
    const float* query = (const float*)d_in[0];
    const float* key   = (const float*)d_in[1];
    const float* value = (const float*)d_in[2];
    const float* ln1w  = (const float*)d_in[3];
    const float* ln1b  = (const float*)d_in[4];
    const float* ln2w  = (const float*)d_in[5];
    const float* ln2b  = (const float*)d_in[6];
    const float* ln3w  = (const float*)d_in[7];
    const float* ln3b  = (const float*)d_in[8];
    const float* wq    = (const float*)d_in[9];
    const float* bq    = (const float*)d_in[10];
    const float* wk    = (const float*)d_in[11];
    const float* bk    = (const float*)d_in[12];
    const float* wv    = (const float*)d_in[13];
    const float* bv    = (const float*)d_in[14];

    float* out = (float*)d_out;
    const size_t XSZ = (size_t)NB * CHW;
    const size_t ASZ = (size_t)NB * HW * HW;

    float* x_out    = nullptr;
    float* attn_out = nullptr;
    size_t osz = (size_t)out_size;
    if (osz >= XSZ + ASZ)      { x_out = out; attn_out = out + XSZ; }
    else if (osz == ASZ)       { attn_out = out; }
    else                       { x_out = out; }

    static int attr_set = 0;
    const int PROJ_SMEM  = (64 * 68 + 256 * 68) * 4;                 // 87040
    const int FLASH_SMEM = (4608 + 4352 + 4608 + 4608 + 128) * 4;    // 73216
    if (!attr_set) {
        cudaFuncSetAttribute(proj_kernel,
                             cudaFuncAttributeMaxDynamicSharedMemorySize, PROJ_SMEM);
        cudaFuncSetAttribute(flash_kernel,
                             cudaFuncAttributeMaxDynamicSharedMemorySize, FLASH_SMEM);
        attr_set = 1;
    }

    ln_kernel<<<NB * 3, 1024>>>(query, key, value, ln1w, ln1b, ln2w, ln2b, ln3w, ln3b);
    proj_kernel<<<dim3(4, NB, 3), 256, PROJ_SMEM>>>(wq, bq, wk, bk, wv, bv);
    flash_kernel<<<dim3(HW / JT, NB), 256, FLASH_SMEM>>>(attn_out, x_out);
}

// round 7
// speedup vs baseline: 2.7615x; 1.3136x over previous
#include <cuda_runtime.h>
#include <math_constants.h>

#define NB  32
#define C   64
#define HW  1024
#define CHW 65536
#define EPS 1e-5f
#define JT  64
#define IC  64
#define LSCALE 0.180336880f   // 0.125 * log2(e)

// ---------------- scratch ----------------------------------------------------
__device__ float g_qn[NB * CHW];
__device__ float g_kn[NB * CHW];
__device__ float g_vn[NB * CHW];
__device__ float g_q [NB * CHW];
__device__ float g_kt[NB * CHW];           // K transposed: [n][i][c]
__device__ float g_v [NB * CHW];
__device__ float g_part[96][4][2];         // LN partial sums

// ---------------- helpers ----------------------------------------------------
__device__ __forceinline__ unsigned f2tf(float x) {
    unsigned u;
    asm("cvt.rna.tf32.f32 %0, %1;" : "=r"(u) : "f"(x));
    return u;
}
__device__ __forceinline__ float ex2(float x) {
    float y;
    asm("ex2.approx.f32 %0, %1;" : "=f"(y) : "f"(x));
    return y;
}
__device__ __forceinline__ void mma_tf32(float* d, const unsigned* a, const unsigned* b) {
    asm volatile(
        "mma.sync.aligned.m16n8k8.row.col.f32.tf32.tf32.f32 "
        "{%0,%1,%2,%3}, {%4,%5,%6,%7}, {%8,%9}, {%0,%1,%2,%3};\n"
        : "+f"(d[0]), "+f"(d[1]), "+f"(d[2]), "+f"(d[3])
        : "r"(a[0]), "r"(a[1]), "r"(a[2]), "r"(a[3]), "r"(b[0]), "r"(b[1]));
}

// ---------------- 1a. LN stats: grid (96, 4), 256 thr -----------------------
__global__ __launch_bounds__(256) void ln_stats_kernel(
    const float* __restrict__ q, const float* __restrict__ k, const float* __restrict__ v)
{
    int t     = blockIdx.x;          // 0..95 : tensor id (n*3 + which)
    int quart = blockIdx.y;          // 0..3
    int which = t % 3, n = t / 3;
    const float* x = (which == 0 ? q : which == 1 ? k : v) + (size_t)n * CHW + quart * 16384;

    int tid = threadIdx.x;
    float s = 0.f, ss = 0.f;
    float4 acc4s = make_float4(0, 0, 0, 0), acc4q = make_float4(0, 0, 0, 0);
    for (int i = tid * 4; i < 16384; i += 256 * 4) {
        float4 val = *(const float4*)(x + i);
        acc4s.x += val.x; acc4s.y += val.y; acc4s.z += val.z; acc4s.w += val.w;
        acc4q.x += val.x * val.x; acc4q.y += val.y * val.y;
        acc4q.z += val.z * val.z; acc4q.w += val.w * val.w;
    }
    s  = acc4s.x + acc4s.y + acc4s.z + acc4s.w;
    ss = acc4q.x + acc4q.y + acc4q.z + acc4q.w;

    __shared__ float sm[256], sm2[256];
    sm[tid] = s; sm2[tid] = ss;
    __syncthreads();
    for (int o = 128; o > 0; o >>= 1) {
        if (tid < o) { sm[tid] += sm[tid + o]; sm2[tid] += sm2[tid + o]; }
        __syncthreads();
    }
    if (tid == 0) { g_part[t][quart][0] = sm[0]; g_part[t][quart][1] = sm2[0]; }
}

// ---------------- 1b. LN apply: grid (96, 4), 256 thr -----------------------
__global__ __launch_bounds__(256) void ln_apply_kernel(
    const float* __restrict__ q, const float* __restrict__ k, const float* __restrict__ v,
    const float* __restrict__ w1, const float* __restrict__ b1,
    const float* __restrict__ w2, const float* __restrict__ b2,
    const float* __restrict__ w3, const float* __restrict__ b3)
{
    int t     = blockIdx.x;
    int quart = blockIdx.y;
    int which = t % 3, n = t / 3;
    const float *x, *w, *b;
    float* dst;
    if (which == 0)      { x = q; w = w1; b = b1; dst = g_qn; }
    else if (which == 1) { x = k; w = w2; b = b2; dst = g_kn; }
    else                 { x = v; w = w3; b = b3; dst = g_vn; }
    size_t off = (size_t)n * CHW + quart * 16384;
    x += off; dst += off;
    w += quart * 16384; b += quart * 16384;

    float s = 0.f, ss = 0.f;
#pragma unroll
    for (int qq = 0; qq < 4; qq++) { s += g_part[t][qq][0]; ss += g_part[t][qq][1]; }
    float mean = s * (1.0f / CHW);
    float var  = ss * (1.0f / CHW) - mean * mean;
    float rstd = rsqrtf(var + EPS);

    int tid = threadIdx.x;
    for (int i = tid * 4; i < 16384; i += 256 * 4) {
        float4 val = *(const float4*)(x + i);
        float4 wv  = *(const float4*)(w + i);
        float4 bv  = *(const float4*)(b + i);
        float4 o4;
        o4.x = (val.x - mean) * rstd * wv.x + bv.x;
        o4.y = (val.y - mean) * rstd * wv.y + bv.y;
        o4.z = (val.z - mean) * rstd * wv.z + bv.z;
        o4.w = (val.w - mean) * rstd * wv.w + bv.w;
        *(float4*)(dst + i) = o4;
    }
}

// ---------------- 2. projection via tf32 mma; K transposed ------------------
__global__ __launch_bounds__(256) void proj_kernel(
    const float* __restrict__ wq, const float* __restrict__ bq,
    const float* __restrict__ wk, const float* __restrict__ bk,
    const float* __restrict__ wv, const float* __restrict__ bv)
{
    extern __shared__ unsigned psm[];
    unsigned* Ws = psm;              // [64 o][68]
    unsigned* Xs = psm + 64 * 68;    // [64 c][264]; T reuse needs 256*68

    int which = blockIdx.z;
    int n     = blockIdx.y;
    int p0    = blockIdx.x * 256;
    const float *src, *W, *B;
    if (which == 0)      { src = g_qn; W = wq; B = bq; }
    else if (which == 1) { src = g_kn; W = wk; B = bk; }
    else                 { src = g_vn; W = wv; B = bv; }
    src += (size_t)n * CHW;

    int tid = threadIdx.x;
    for (int idx = tid; idx < 64 * 16; idx += 256) {
        int o = idx >> 4, c4 = (idx & 15) << 2;
        float4 v = *(const float4*)(W + o * C + c4);
        *(uint4*)(Ws + o * 68 + c4) =
            make_uint4(f2tf(v.x), f2tf(v.y), f2tf(v.z), f2tf(v.w));
    }
    for (int idx = tid; idx < 64 * 64; idx += 256) {
        int c = idx >> 6, p4 = (idx & 63) << 2;
        float4 v = *(const float4*)(src + c * HW + p0 + p4);
        *(uint4*)(Xs + c * 264 + p4) =
            make_uint4(f2tf(v.x), f2tf(v.y), f2tf(v.z), f2tf(v.w));
    }
    __syncthreads();

    int wid = tid >> 5, lane = tid & 31;
    int g = lane >> 2, tig = lane & 3;
    int wn = wid * 32;

    float acc[4][4][4] = {};
#pragma unroll
    for (int kk = 0; kk < 8; kk++) {
        int c0 = kk * 8;
        unsigned a[4][4], b[4][2];
#pragma unroll
        for (int mf = 0; mf < 4; mf++) {
            int r = mf * 16 + g;
            a[mf][0] = Ws[r * 68 + c0 + tig];
            a[mf][1] = Ws[(r + 8) * 68 + c0 + tig];
            a[mf][2] = Ws[r * 68 + c0 + tig + 4];
            a[mf][3] = Ws[(r + 8) * 68 + c0 + tig + 4];
        }
#pragma unroll
        for (int nf = 0; nf < 4; nf++) {
            int col = wn + nf * 8 + g;
            b[nf][0] = Xs[(c0 + tig) * 264 + col];
            b[nf][1] = Xs[(c0 + tig + 4) * 264 + col];
        }
#pragma unroll
        for (int mf = 0; mf < 4; mf++)
#pragma unroll
            for (int nf = 0; nf < 4; nf++)
                mma_tf32(acc[mf][nf], a[mf], b[nf]);
    }

    if (which != 1) {
        float* dst = (which == 0 ? g_q : g_v) + (size_t)n * CHW;
#pragma unroll
        for (int mf = 0; mf < 4; mf++) {
            int o = mf * 16 + g;
            float b0 = B[o], b1 = B[o + 8];
#pragma unroll
            for (int nf = 0; nf < 4; nf++) {
                int p = p0 + wn + nf * 8 + 2 * tig;
                *(float2*)(dst + o * HW + p) =
                    make_float2(acc[mf][nf][0] + b0, acc[mf][nf][1] + b0);
                *(float2*)(dst + (o + 8) * HW + p) =
                    make_float2(acc[mf][nf][2] + b1, acc[mf][nf][3] + b1);
            }
        }
    } else {
        __syncthreads();
        float* T = (float*)Xs;   // [256 p][68]
#pragma unroll
        for (int mf = 0; mf < 4; mf++) {
            int o = mf * 16 + g;
            float b0 = B[o], b1 = B[o + 8];
#pragma unroll
            for (int nf = 0; nf < 4; nf++) {
                int p = wn + nf * 8 + 2 * tig;
                T[p * 68 + o]           = acc[mf][nf][0] + b0;
                T[(p + 1) * 68 + o]     = acc[mf][nf][1] + b0;
                T[p * 68 + o + 8]       = acc[mf][nf][2] + b1;
                T[(p + 1) * 68 + o + 8] = acc[mf][nf][3] + b1;
            }
        }
        __syncthreads();
        float* dst = g_kt + (size_t)n * CHW;
        for (int idx = tid; idx < 256 * 16; idx += 256) {
            int p = idx >> 4, c4 = (idx & 15) << 2;
            float4 v = make_float4(T[p * 68 + c4], T[p * 68 + c4 + 1],
                                   T[p * 68 + c4 + 2], T[p * 68 + c4 + 3]);
            *(float4*)(dst + (size_t)(p0 + p) * C + c4) = v;
        }
    }
}

// ---------------- 3. flash, no-max softmax, pipelined ------------------------
// grid = (16 jt, NB), block 256 (8 warps)
// smem u32: Qs[64*72]=4608 | K0[64*68]=4352 | K1=4352 | V0[64*72]=4608 | V1=4608
//           | Ps[64*72]=4608 (fp32) | rcol 64 | sums 128  => 27328 u32 = 109312 B
#define OFF_Q   0
#define OFF_K0  4608
#define OFF_K1  (4608 + 4352)
#define OFF_V0  (4608 + 8704)
#define OFF_V1  (4608 + 8704 + 4608)
#define OFF_P   (4608 + 8704 + 9216)
#define OFF_RC  (OFF_P + 4608)
#define OFF_SUM (OFF_RC + 64)
#define FLASH_U32 (OFF_SUM + 128)

__global__ __launch_bounds__(256) void flash_kernel(
    float* __restrict__ attn_out, float* __restrict__ xout)
{
    extern __shared__ unsigned fsm[];
    unsigned* Qs  = fsm + OFF_Q;
    float*    Psf = (float*)(fsm + OFF_P);
    float*    rcol = (float*)(fsm + OFF_RC);
    float*    sums = (float*)(fsm + OFF_SUM);

    int n  = blockIdx.y;
    int j0 = blockIdx.x * JT;
    int tid = threadIdx.x;
    const float* kt = g_kt + (size_t)n * CHW;
    const float* qp = g_q  + (size_t)n * CHW;
    const float* vp = g_v  + (size_t)n * CHW;

    // load indices for the 4 per-thread float4s of a 64x16(f4) K chunk
    int li[4], lc[4];
#pragma unroll
    for (int t = 0; t < 4; t++) {
        int idx = tid + t * 256;
        li[t] = idx >> 4; lc[t] = (idx & 15) << 2;
    }

    // Q stripe, pre-scaled
    for (int idx = tid; idx < 64 * 16; idx += 256) {
        int c = idx >> 4, j4 = (idx & 15) << 2;
        float4 v = *(const float4*)(qp + c * HW + j0 + j4);
        *(uint4*)(Qs + c * 72 + j4) =
            make_uint4(f2tf(v.x * LSCALE), f2tf(v.y * LSCALE),
                       f2tf(v.z * LSCALE), f2tf(v.w * LSCALE));
    }

    int wid = tid >> 5, lane = tid & 31;
    int g = lane >> 2, tig = lane & 3;
    int wm = (wid & 1) * 32;
    int wn = (wid >> 1) * 16;

    // ---------------- Phase A: column sum of exp2(logits) -------------------
    float4 kr[1]; float4 kr4[4];
    (void)kr;
#pragma unroll
    for (int t = 0; t < 4; t++)
        kr4[t] = *(const float4*)(kt + (size_t)li[t] * C + lc[t]);
    {
        unsigned* K0 = fsm + OFF_K0;
#pragma unroll
        for (int t = 0; t < 4; t++)
            *(uint4*)(K0 + li[t] * 68 + lc[t]) =
                make_uint4(f2tf(kr4[t].x), f2tf(kr4[t].y), f2tf(kr4[t].z), f2tf(kr4[t].w));
    }
    __syncthreads();

    float s_run[2][2] = {{0.f, 0.f}, {0.f, 0.f}};

    for (int ch = 0; ch < 16; ch++) {
        unsigned* Ks = fsm + ((ch & 1) ? OFF_K1 : OFF_K0);
        unsigned* Kn = fsm + ((ch & 1) ? OFF_K0 : OFF_K1);
        if (ch < 15) {
            int i0n = (ch + 1) * IC;
#pragma unroll
            for (int t = 0; t < 4; t++)
                kr4[t] = *(const float4*)(kt + (size_t)(i0n + li[t]) * C + lc[t]);
        }

        float acc1[2][2][4] = {};
#pragma unroll
        for (int kk = 0; kk < 8; kk++) {
            int c0 = kk * 8;
            unsigned a[2][4], b[2][2];
#pragma unroll
            for (int mf = 0; mf < 2; mf++) {
                int r = wm + mf * 16 + g;
                a[mf][0] = Ks[r * 68 + c0 + tig];
                a[mf][1] = Ks[(r + 8) * 68 + c0 + tig];
                a[mf][2] = Ks[r * 68 + c0 + tig + 4];
                a[mf][3] = Ks[(r + 8) * 68 + c0 + tig + 4];
            }
#pragma unroll
            for (int nf = 0; nf < 2; nf++) {
                int col = wn + nf * 8 + g;
                b[nf][0] = Qs[(c0 + tig) * 72 + col];
                b[nf][1] = Qs[(c0 + tig + 4) * 72 + col];
            }
#pragma unroll
            for (int mf = 0; mf < 2; mf++)
#pragma unroll
                for (int nf = 0; nf < 2; nf++)
                    mma_tf32(acc1[mf][nf], a[mf], b[nf]);
        }

#pragma unroll
        for (int nf = 0; nf < 2; nf++) {
            s_run[nf][0] += ex2(acc1[0][nf][0]) + ex2(acc1[0][nf][2])
                          + ex2(acc1[1][nf][0]) + ex2(acc1[1][nf][2]);
            s_run[nf][1] += ex2(acc1[0][nf][1]) + ex2(acc1[0][nf][3])
                          + ex2(acc1[1][nf][1]) + ex2(acc1[1][nf][3]);
        }

        if (ch < 15) {
#pragma unroll
            for (int t = 0; t < 4; t++)
                *(uint4*)(Kn + li[t] * 68 + lc[t]) =
                    make_uint4(f2tf(kr4[t].x), f2tf(kr4[t].y), f2tf(kr4[t].z), f2tf(kr4[t].w));
        }
        __syncthreads();
    }

    // reduce over g-lanes (masks 4,8,16 change g only)
#pragma unroll
    for (int mask = 4; mask <= 16; mask <<= 1)
#pragma unroll
        for (int nf = 0; nf < 2; nf++)
#pragma unroll
            for (int par = 0; par < 2; par++)
                s_run[nf][par] += __shfl_xor_sync(0xFFFFFFFF, s_run[nf][par], mask);

    if (g == 0) {
#pragma unroll
        for (int nf = 0; nf < 2; nf++)
#pragma unroll
            for (int par = 0; par < 2; par++)
                sums[(wid & 1) * 64 + wn + nf * 8 + 2 * tig + par] = s_run[nf][par];
    }
    __syncthreads();
    if (tid < 64) rcol[tid] = 1.0f / (sums[tid] + sums[64 + tid]);
    __syncthreads();

    float rj[2][2];
#pragma unroll
    for (int nf = 0; nf < 2; nf++)
#pragma unroll
        for (int par = 0; par < 2; par++)
            rj[nf][par] = rcol[wn + nf * 8 + 2 * tig + par];

    // ---------------- Phase B: recompute, probs out, V@P ---------------------
    float* ap = attn_out ? attn_out + (size_t)n * HW * HW + j0 : nullptr;
    float acc2[2][2][4] = {};
    float4 vr4[4];

#pragma unroll
    for (int t = 0; t < 4; t++) {
        kr4[t] = *(const float4*)(kt + (size_t)li[t] * C + lc[t]);
        vr4[t] = *(const float4*)(vp + li[t] * HW + lc[t]);   // [c][i] layout
    }
    {
        unsigned* K0 = fsm + OFF_K0;
        unsigned* V0 = fsm + OFF_V0;
#pragma unroll
        for (int t = 0; t < 4; t++) {
            *(uint4*)(K0 + li[t] * 68 + lc[t]) =
                make_uint4(f2tf(kr4[t].x), f2tf(kr4[t].y), f2tf(kr4[t].z), f2tf(kr4[t].w));
            *(uint4*)(V0 + li[t] * 72 + lc[t]) =
                make_uint4(f2tf(vr4[t].x), f2tf(vr4[t].y), f2tf(vr4[t].z), f2tf(vr4[t].w));
        }
    }
    __syncthreads();

    for (int ch = 0; ch < 16; ch++) {
        int i0 = ch * IC;
        unsigned* Ks = fsm + ((ch & 1) ? OFF_K1 : OFF_K0);
        unsigned* Kn = fsm + ((ch & 1) ? OFF_K0 : OFF_K1);
        unsigned* Vs = fsm + ((ch & 1) ? OFF_V1 : OFF_V0);
        unsigned* Vn = fsm + ((ch & 1) ? OFF_V0 : OFF_V1);

        if (ch < 15) {
            int i0n = i0 + IC;
#pragma unroll
            for (int t = 0; t < 4; t++) {
                kr4[t] = *(const float4*)(kt + (size_t)(i0n + li[t]) * C + lc[t]);
                vr4[t] = *(const float4*)(vp + li[t] * HW + i0n + lc[t]);
            }
        }

        float acc1[2][2][4] = {};
#pragma unroll
        for (int kk = 0; kk < 8; kk++) {
            int c0 = kk * 8;
            unsigned a[2][4], b[2][2];
#pragma unroll
            for (int mf = 0; mf < 2; mf++) {
                int r = wm + mf * 16 + g;
                a[mf][0] = Ks[r * 68 + c0 + tig];
                a[mf][1] = Ks[(r + 8) * 68 + c0 + tig];
                a[mf][2] = Ks[r * 68 + c0 + tig + 4];
                a[mf][3] = Ks[(r + 8) * 68 + c0 + tig + 4];
            }
#pragma unroll
            for (int nf = 0; nf < 2; nf++) {
                int col = wn + nf * 8 + g;
                b[nf][0] = Qs[(c0 + tig) * 72 + col];
                b[nf][1] = Qs[(c0 + tig + 4) * 72 + col];
            }
#pragma unroll
            for (int mf = 0; mf < 2; mf++)
#pragma unroll
                for (int nf = 0; nf < 2; nf++)
                    mma_tf32(acc1[mf][nf], a[mf], b[nf]);
        }

        // probs (fp32) into Ps
#pragma unroll
        for (int mf = 0; mf < 2; mf++) {
            int il = wm + mf * 16 + g;
#pragma unroll
            for (int nf = 0; nf < 2; nf++) {
                int col = wn + nf * 8 + 2 * tig;
                float p0 = ex2(acc1[mf][nf][0]) * rj[nf][0];
                float p1 = ex2(acc1[mf][nf][1]) * rj[nf][1];
                float p2 = ex2(acc1[mf][nf][2]) * rj[nf][0];
                float p3 = ex2(acc1[mf][nf][3]) * rj[nf][1];
                *(float2*)(Psf + il * 72 + col)       = make_float2(p0, p1);
                *(float2*)(Psf + (il + 8) * 72 + col) = make_float2(p2, p3);
            }
        }

        if (ch < 15) {
#pragma unroll
            for (int t = 0; t < 4; t++) {
                *(uint4*)(Kn + li[t] * 68 + lc[t]) =
                    make_uint4(f2tf(kr4[t].x), f2tf(kr4[t].y), f2tf(kr4[t].z), f2tf(kr4[t].w));
                *(uint4*)(Vn + li[t] * 72 + lc[t]) =
                    make_uint4(f2tf(vr4[t].x), f2tf(vr4[t].y), f2tf(vr4[t].z), f2tf(vr4[t].w));
            }
        }
        __syncthreads();

        // coalesced probs -> attn_out
        if (ap) {
#pragma unroll
            for (int t = 0; t < 4; t++) {
                int ii = li[t], j4 = lc[t];
                *(float4*)(ap + (size_t)(i0 + ii) * HW + j4) =
                    *(const float4*)(Psf + ii * 72 + j4);
            }
        }

        if (xout) {
#pragma unroll
            for (int kk = 0; kk < 8; kk++) {
                int k0 = kk * 8;
                unsigned a[2][4], b[2][2];
#pragma unroll
                for (int mf = 0; mf < 2; mf++) {
                    int r = wm + mf * 16 + g;   // c row
                    a[mf][0] = Vs[r * 72 + k0 + tig];
                    a[mf][1] = Vs[(r + 8) * 72 + k0 + tig];
                    a[mf][2] = Vs[r * 72 + k0 + tig + 4];
                    a[mf][3] = Vs[(r + 8) * 72 + k0 + tig + 4];
                }
#pragma unroll
                for (int nf = 0; nf < 2; nf++) {
                    int col = wn + nf * 8 + g;
                    b[nf][0] = f2tf(Psf[(k0 + tig) * 72 + col]);
                    b[nf][1] = f2tf(Psf[(k0 + tig + 4) * 72 + col]);
                }
#pragma unroll
                for (int mf = 0; mf < 2; mf++)
#pragma unroll
                    for (int nf = 0; nf < 2; nf++)
                        mma_tf32(acc2[mf][nf], a[mf], b[nf]);
            }
        }
        __syncthreads();
    }

    if (!xout) return;
    const float* qn = g_qn + (size_t)n * CHW;
    float* xp = xout + (size_t)n * CHW;
#pragma unroll
    for (int mf = 0; mf < 2; mf++) {
        int c = wm + mf * 16 + g;
#pragma unroll
        for (int nf = 0; nf < 2; nf++) {
            int j = j0 + wn + nf * 8 + 2 * tig;
            float2 q0 = *(const float2*)(qn + c * HW + j);
            float2 q1 = *(const float2*)(qn + (c + 8) * HW + j);
            *(float2*)(xp + c * HW + j) =
                make_float2(acc2[mf][nf][0] + q0.x, acc2[mf][nf][1] + q0.y);
            *(float2*)(xp + (c + 8) * HW + j) =
                make_float2(acc2[mf][nf][2] + q1.x, acc2[mf][nf][3] + q1.y);
        }
    }
}

// ---------------------------------------------------------------------------
extern "C" void kernel_launch(void* const* d_in, const int* in_sizes, int n_in,
                              void* d_out, int out_size)
{
    const float* query = (const float*)d_in[0];
    const float* key   = (const float*)d_in[1];
    const float* value = (const float*)d_in[2];
    const float* ln1w  = (const float*)d_in[3];
    const float* ln1b  = (const float*)d_in[4];
    const float* ln2w  = (const float*)d_in[5];
    const float* ln2b  = (const float*)d_in[6];
    const float* ln3w  = (const float*)d_in[7];
    const float* ln3b  = (const float*)d_in[8];
    const float* wq    = (const float*)d_in[9];
    const float* bq    = (const float*)d_in[10];
    const float* wk    = (const float*)d_in[11];
    const float* bk    = (const float*)d_in[12];
    const float* wv    = (const float*)d_in[13];
    const float* bv    = (const float*)d_in[14];

    float* out = (float*)d_out;
    const size_t XSZ = (size_t)NB * CHW;
    const size_t ASZ = (size_t)NB * HW * HW;

    float* x_out    = nullptr;
    float* attn_out = nullptr;
    size_t osz = (size_t)out_size;
    if (osz >= XSZ + ASZ)      { x_out = out; attn_out = out + XSZ; }
    else if (osz == ASZ)       { attn_out = out; }
    else                       { x_out = out; }

    static int attr_set = 0;
    const int PROJ_SMEM  = (64 * 68 + 256 * 68) * 4;   // 87040
    const int FLASH_SMEM = FLASH_U32 * 4;              // 109312
    if (!attr_set) {
        cudaFuncSetAttribute(proj_kernel,
                             cudaFuncAttributeMaxDynamicSharedMemorySize, PROJ_SMEM);
        cudaFuncSetAttribute(flash_kernel,
                             cudaFuncAttributeMaxDynamicSharedMemorySize, FLASH_SMEM);
        attr_set = 1;
    }

    ln_stats_kernel<<<dim3(96, 4), 256>>>(query, key, value);
    ln_apply_kernel<<<dim3(96, 4), 256>>>(query, key, value,
                                          ln1w, ln1b, ln2w, ln2b, ln3w, ln3b);
    proj_kernel<<<dim3(4, NB, 3), 256, PROJ_SMEM>>>(wq, bq, wk, bk, wv, bv);
    flash_kernel<<<dim3(HW / JT, NB), 256, FLASH_SMEM>>>(attn_out, x_out);
}

// round 8
// speedup vs baseline: 3.0072x; 1.0890x over previous
#include <cuda_runtime.h>
#include <math_constants.h>

#define NB  32
#define C   64
#define HW  1024
#define CHW 65536
#define EPS 1e-5f
#define JT  64
#define IC  64
#define LSCALE 0.180336880f   // 0.125 * log2(e)

// ---------------- scratch ----------------------------------------------------
__device__ float g_qn[NB * CHW];
__device__ float g_kn[NB * CHW];
__device__ float g_vn[NB * CHW];
__device__ float g_q [NB * CHW];           // tf32-rounded, pre-scaled by LSCALE
__device__ float g_kt[NB * CHW];           // K transposed [n][i][c], tf32-rounded
__device__ float g_v [NB * CHW];           // tf32-rounded
__device__ float g_part[96][4][2];         // LN partial sums
__device__ float g_rs[NB * HW];            // per-column 1/S

// ---------------- helpers ----------------------------------------------------
__device__ __forceinline__ unsigned f2tf(float x) {
    unsigned u;
    asm("cvt.rna.tf32.f32 %0, %1;" : "=r"(u) : "f"(x));
    return u;
}
__device__ __forceinline__ float ex2(float x) {
    float y;
    asm("ex2.approx.f32 %0, %1;" : "=f"(y) : "f"(x));
    return y;
}
__device__ __forceinline__ void mma_tf32(float* d, const unsigned* a, const unsigned* b) {
    asm volatile(
        "mma.sync.aligned.m16n8k8.row.col.f32.tf32.tf32.f32 "
        "{%0,%1,%2,%3}, {%4,%5,%6,%7}, {%8,%9}, {%0,%1,%2,%3};\n"
        : "+f"(d[0]), "+f"(d[1]), "+f"(d[2]), "+f"(d[3])
        : "r"(a[0]), "r"(a[1]), "r"(a[2]), "r"(a[3]), "r"(b[0]), "r"(b[1]));
}
__device__ __forceinline__ void cp16(unsigned dst, const void* src) {
    asm volatile("cp.async.cg.shared.global [%0], [%1], 16;" :: "r"(dst), "l"(src));
}
#define CP_COMMIT() asm volatile("cp.async.commit_group;")
#define CP_WAIT0()  asm volatile("cp.async.wait_group 0;")

// ---------------- 1a. LN stats: grid (96, 4), 256 thr -----------------------
__global__ __launch_bounds__(256) void ln_stats_kernel(
    const float* __restrict__ q, const float* __restrict__ k, const float* __restrict__ v)
{
    int t     = blockIdx.x;
    int quart = blockIdx.y;
    int which = t % 3, n = t / 3;
    const float* x = (which == 0 ? q : which == 1 ? k : v) + (size_t)n * CHW + quart * 16384;

    int tid = threadIdx.x;
    float4 a4 = make_float4(0, 0, 0, 0), q4 = make_float4(0, 0, 0, 0);
    for (int i = tid * 4; i < 16384; i += 256 * 4) {
        float4 val = *(const float4*)(x + i);
        a4.x += val.x; a4.y += val.y; a4.z += val.z; a4.w += val.w;
        q4.x += val.x * val.x; q4.y += val.y * val.y;
        q4.z += val.z * val.z; q4.w += val.w * val.w;
    }
    float s  = a4.x + a4.y + a4.z + a4.w;
    float ss = q4.x + q4.y + q4.z + q4.w;

    __shared__ float sm[256], sm2[256];
    sm[tid] = s; sm2[tid] = ss;
    __syncthreads();
    for (int o = 128; o > 0; o >>= 1) {
        if (tid < o) { sm[tid] += sm[tid + o]; sm2[tid] += sm2[tid + o]; }
        __syncthreads();
    }
    if (tid == 0) { g_part[t][quart][0] = sm[0]; g_part[t][quart][1] = sm2[0]; }
}

// ---------------- 1b. LN apply: grid (96, 4), 256 thr -----------------------
__global__ __launch_bounds__(256) void ln_apply_kernel(
    const float* __restrict__ q, const float* __restrict__ k, const float* __restrict__ v,
    const float* __restrict__ w1, const float* __restrict__ b1,
    const float* __restrict__ w2, const float* __restrict__ b2,
    const float* __restrict__ w3, const float* __restrict__ b3)
{
    int t     = blockIdx.x;
    int quart = blockIdx.y;
    int which = t % 3, n = t / 3;
    const float *x, *w, *b;
    float* dst;
    if (which == 0)      { x = q; w = w1; b = b1; dst = g_qn; }
    else if (which == 1) { x = k; w = w2; b = b2; dst = g_kn; }
    else                 { x = v; w = w3; b = b3; dst = g_vn; }
    size_t off = (size_t)n * CHW + quart * 16384;
    x += off; dst += off;
    w += quart * 16384; b += quart * 16384;

    float s = 0.f, ss = 0.f;
#pragma unroll
    for (int qq = 0; qq < 4; qq++) { s += g_part[t][qq][0]; ss += g_part[t][qq][1]; }
    float mean = s * (1.0f / CHW);
    float var  = ss * (1.0f / CHW) - mean * mean;
    float rstd = rsqrtf(var + EPS);

    int tid = threadIdx.x;
    for (int i = tid * 4; i < 16384; i += 256 * 4) {
        float4 val = *(const float4*)(x + i);
        float4 wv  = *(const float4*)(w + i);
        float4 bv  = *(const float4*)(b + i);
        float4 o4;
        o4.x = (val.x - mean) * rstd * wv.x + bv.x;
        o4.y = (val.y - mean) * rstd * wv.y + bv.y;
        o4.z = (val.z - mean) * rstd * wv.z + bv.z;
        o4.w = (val.w - mean) * rstd * wv.w + bv.w;
        *(float4*)(dst + i) = o4;
    }
}

// ---------------- 2. projection; outputs tf32-prerounded --------------------
__global__ __launch_bounds__(256) void proj_kernel(
    const float* __restrict__ wq, const float* __restrict__ bq,
    const float* __restrict__ wk, const float* __restrict__ bk,
    const float* __restrict__ wv, const float* __restrict__ bv)
{
    extern __shared__ unsigned psm[];
    unsigned* Ws = psm;              // [64 o][68]
    unsigned* Xs = psm + 64 * 68;    // [64 c][264]; T reuse needs 256*68

    int which = blockIdx.z;
    int n     = blockIdx.y;
    int p0    = blockIdx.x * 256;
    const float *src, *W, *B;
    if (which == 0)      { src = g_qn; W = wq; B = bq; }
    else if (which == 1) { src = g_kn; W = wk; B = bk; }
    else                 { src = g_vn; W = wv; B = bv; }
    src += (size_t)n * CHW;
    float wscale = (which == 0) ? LSCALE : 1.0f;

    int tid = threadIdx.x;
    for (int idx = tid; idx < 64 * 16; idx += 256) {
        int o = idx >> 4, c4 = (idx & 15) << 2;
        float4 v = *(const float4*)(W + o * C + c4);
        *(uint4*)(Ws + o * 68 + c4) =
            make_uint4(f2tf(v.x * wscale), f2tf(v.y * wscale),
                       f2tf(v.z * wscale), f2tf(v.w * wscale));
    }
    for (int idx = tid; idx < 64 * 64; idx += 256) {
        int c = idx >> 6, p4 = (idx & 63) << 2;
        float4 v = *(const float4*)(src + c * HW + p0 + p4);
        *(uint4*)(Xs + c * 264 + p4) =
            make_uint4(f2tf(v.x), f2tf(v.y), f2tf(v.z), f2tf(v.w));
    }
    __syncthreads();

    int wid = tid >> 5, lane = tid & 31;
    int g = lane >> 2, tig = lane & 3;
    int wn = wid * 32;

    float acc[4][4][4] = {};
#pragma unroll
    for (int kk = 0; kk < 8; kk++) {
        int c0 = kk * 8;
        unsigned a[4][4], b[4][2];
#pragma unroll
        for (int mf = 0; mf < 4; mf++) {
            int r = mf * 16 + g;
            a[mf][0] = Ws[r * 68 + c0 + tig];
            a[mf][1] = Ws[(r + 8) * 68 + c0 + tig];
            a[mf][2] = Ws[r * 68 + c0 + tig + 4];
            a[mf][3] = Ws[(r + 8) * 68 + c0 + tig + 4];
        }
#pragma unroll
        for (int nf = 0; nf < 4; nf++) {
            int col = wn + nf * 8 + g;
            b[nf][0] = Xs[(c0 + tig) * 264 + col];
            b[nf][1] = Xs[(c0 + tig + 4) * 264 + col];
        }
#pragma unroll
        for (int mf = 0; mf < 4; mf++)
#pragma unroll
            for (int nf = 0; nf < 4; nf++)
                mma_tf32(acc[mf][nf], a[mf], b[nf]);
    }

    if (which != 1) {
        float* dst = (which == 0 ? g_q : g_v) + (size_t)n * CHW;
#pragma unroll
        for (int mf = 0; mf < 4; mf++) {
            int o = mf * 16 + g;
            float b0 = B[o] * wscale, b1 = B[o + 8] * wscale;
#pragma unroll
            for (int nf = 0; nf < 4; nf++) {
                int p = p0 + wn + nf * 8 + 2 * tig;
                *(uint2*)(dst + o * HW + p) =
                    make_uint2(f2tf(acc[mf][nf][0] + b0), f2tf(acc[mf][nf][1] + b0));
                *(uint2*)(dst + (o + 8) * HW + p) =
                    make_uint2(f2tf(acc[mf][nf][2] + b1), f2tf(acc[mf][nf][3] + b1));
            }
        }
    } else {
        __syncthreads();
        float* T = (float*)Xs;   // [256 p][68]
#pragma unroll
        for (int mf = 0; mf < 4; mf++) {
            int o = mf * 16 + g;
            float b0 = B[o], b1 = B[o + 8];
#pragma unroll
            for (int nf = 0; nf < 4; nf++) {
                int p = wn + nf * 8 + 2 * tig;
                T[p * 68 + o]           = acc[mf][nf][0] + b0;
                T[(p + 1) * 68 + o]     = acc[mf][nf][1] + b0;
                T[p * 68 + o + 8]       = acc[mf][nf][2] + b1;
                T[(p + 1) * 68 + o + 8] = acc[mf][nf][3] + b1;
            }
        }
        __syncthreads();
        float* dst = g_kt + (size_t)n * CHW;
        for (int idx = tid; idx < 256 * 16; idx += 256) {
            int p = idx >> 4, c4 = (idx & 15) << 2;
            uint4 v = make_uint4(f2tf(T[p * 68 + c4]),     f2tf(T[p * 68 + c4 + 1]),
                                 f2tf(T[p * 68 + c4 + 2]), f2tf(T[p * 68 + c4 + 3]));
            *(uint4*)(dst + (size_t)(p0 + p) * C + c4) = v;
        }
    }
}

// ---------------- 3. one-pass flash, cp.async, Q in regs ---------------------
// grid = (16 jt, NB), block 256
// smem u32: QP[64*72]=4608 (Q staging then Ps) | K0,K1[64*68] | V0,V1[64*72]
//           | sums 128 | rcol 64  => 22720 u32 = 90880 B
#define OFF_QP  0
#define OFF_K0  4608
#define OFF_K1  (4608 + 4352)
#define OFF_V0  (4608 + 8704)
#define OFF_V1  (4608 + 8704 + 4608)
#define OFF_SUM (4608 + 8704 + 9216)
#define OFF_RC  (OFF_SUM + 128)
#define FLASH_U32 (OFF_RC + 64)

__global__ __launch_bounds__(256, 2) void flash_kernel(
    float* __restrict__ attn_out, float* __restrict__ xout)
{
    extern __shared__ unsigned fsm[];
    unsigned* Qs  = fsm + OFF_QP;
    float*    Psf = (float*)(fsm + OFF_QP);
    unsigned* Ps  = fsm + OFF_QP;
    float*    sums = (float*)(fsm + OFF_SUM);
    float*    rcol = (float*)(fsm + OFF_RC);

    int n  = blockIdx.y;
    int j0 = blockIdx.x * JT;
    int tid = threadIdx.x;
    const float* kt = g_kt + (size_t)n * CHW;
    const float* qp = g_q  + (size_t)n * CHW;
    const float* vp = g_v  + (size_t)n * CHW;

    unsigned sb = (unsigned)__cvta_generic_to_shared(fsm);

    int li[4], lc[4];
#pragma unroll
    for (int t = 0; t < 4; t++) {
        int idx = tid + t * 256;
        li[t] = idx >> 4; lc[t] = (idx & 15) << 2;
    }

    // preload chunk 0 (K,V) via cp.async
#pragma unroll
    for (int t = 0; t < 4; t++) {
        cp16(sb + ((OFF_K0 + li[t] * 68 + lc[t]) << 2), kt + (size_t)li[t] * C + lc[t]);
        cp16(sb + ((OFF_V0 + li[t] * 72 + lc[t]) << 2), vp + li[t] * HW + lc[t]);
    }
    CP_COMMIT();

    // Q staging (values already tf32 bits, pre-scaled)
    for (int idx = tid; idx < 64 * 16; idx += 256) {
        int c = idx >> 4, j4 = (idx & 15) << 2;
        *(uint4*)(Qs + c * 72 + j4) = *(const uint4*)(qp + c * HW + j0 + j4);
    }
    __syncthreads();

    int wid = tid >> 5, lane = tid & 31;
    int g = lane >> 2, tig = lane & 3;
    int wm = (wid & 1) * 32;
    int wn = (wid >> 1) * 16;

    // Q fragments to registers (32 regs)
    unsigned Qb[8][2][2];
#pragma unroll
    for (int kk = 0; kk < 8; kk++)
#pragma unroll
        for (int nf = 0; nf < 2; nf++) {
            int col = wn + nf * 8 + g;
            Qb[kk][nf][0] = Qs[(kk * 8 + tig) * 72 + col];
            Qb[kk][nf][1] = Qs[(kk * 8 + tig + 4) * 72 + col];
        }

    float* ap = attn_out ? attn_out + (size_t)n * HW * HW + j0 : nullptr;
    float s_run[2][2] = {{0.f, 0.f}, {0.f, 0.f}};
    float acc2[2][2][4] = {};

    for (int ch = 0; ch < 16; ch++) {
        CP_WAIT0();
        __syncthreads();   // chunk ch ready; all warps done with Ps/buffers of ch-1

        if (ch < 15) {
            int i0n = (ch + 1) * IC;
            unsigned koff = ((ch + 1) & 1) ? OFF_K1 : OFF_K0;
            unsigned voff = ((ch + 1) & 1) ? OFF_V1 : OFF_V0;
#pragma unroll
            for (int t = 0; t < 4; t++) {
                cp16(sb + ((koff + li[t] * 68 + lc[t]) << 2),
                     kt + (size_t)(i0n + li[t]) * C + lc[t]);
                cp16(sb + ((voff + li[t] * 72 + lc[t]) << 2),
                     vp + li[t] * HW + i0n + lc[t]);
            }
            CP_COMMIT();
        }

        unsigned* Ks = fsm + ((ch & 1) ? OFF_K1 : OFF_K0);
        unsigned* Vs = fsm + ((ch & 1) ? OFF_V1 : OFF_V0);
        int i0 = ch * IC;

        // mma1: logits
        float acc1[2][2][4] = {};
#pragma unroll
        for (int kk = 0; kk < 8; kk++) {
            int c0 = kk * 8;
            unsigned a[2][4];
#pragma unroll
            for (int mf = 0; mf < 2; mf++) {
                int r = wm + mf * 16 + g;
                a[mf][0] = Ks[r * 68 + c0 + tig];
                a[mf][1] = Ks[(r + 8) * 68 + c0 + tig];
                a[mf][2] = Ks[r * 68 + c0 + tig + 4];
                a[mf][3] = Ks[(r + 8) * 68 + c0 + tig + 4];
            }
#pragma unroll
            for (int mf = 0; mf < 2; mf++)
#pragma unroll
                for (int nf = 0; nf < 2; nf++)
                    mma_tf32(acc1[mf][nf], a[mf], Qb[kk][nf]);
        }

        // unnormalized probs: STG to attn, STS tf32 to Ps, accumulate sums
#pragma unroll
        for (int mf = 0; mf < 2; mf++) {
            int il = wm + mf * 16 + g;
#pragma unroll
            for (int nf = 0; nf < 2; nf++) {
                int col = wn + nf * 8 + 2 * tig;
                float p0 = ex2(acc1[mf][nf][0]);
                float p1 = ex2(acc1[mf][nf][1]);
                float p2 = ex2(acc1[mf][nf][2]);
                float p3 = ex2(acc1[mf][nf][3]);
                s_run[nf][0] += p0 + p2;
                s_run[nf][1] += p1 + p3;
                if (ap) {
                    *(float2*)(ap + (size_t)(i0 + il) * HW + col)     = make_float2(p0, p1);
                    *(float2*)(ap + (size_t)(i0 + il + 8) * HW + col) = make_float2(p2, p3);
                }
                *(uint2*)(Ps + il * 72 + col)       = make_uint2(f2tf(p0), f2tf(p1));
                *(uint2*)(Ps + (il + 8) * 72 + col) = make_uint2(f2tf(p2), f2tf(p3));
            }
        }
        __syncthreads();   // Ps complete

        if (xout) {
#pragma unroll
            for (int kk = 0; kk < 8; kk++) {
                int k0 = kk * 8;
                unsigned a[2][4], b[2][2];
#pragma unroll
                for (int mf = 0; mf < 2; mf++) {
                    int r = wm + mf * 16 + g;   // c row
                    a[mf][0] = Vs[r * 72 + k0 + tig];
                    a[mf][1] = Vs[(r + 8) * 72 + k0 + tig];
                    a[mf][2] = Vs[r * 72 + k0 + tig + 4];
                    a[mf][3] = Vs[(r + 8) * 72 + k0 + tig + 4];
                }
#pragma unroll
                for (int nf = 0; nf < 2; nf++) {
                    int col = wn + nf * 8 + g;
                    b[nf][0] = Ps[(k0 + tig) * 72 + col];
                    b[nf][1] = Ps[(k0 + tig + 4) * 72 + col];
                }
#pragma unroll
                for (int mf = 0; mf < 2; mf++)
#pragma unroll
                    for (int nf = 0; nf < 2; nf++)
                        mma_tf32(acc2[mf][nf], a[mf], b[nf]);
            }
        }
    }

    // column sums -> 1/S
#pragma unroll
    for (int mask = 4; mask <= 16; mask <<= 1)
#pragma unroll
        for (int nf = 0; nf < 2; nf++)
#pragma unroll
            for (int par = 0; par < 2; par++)
                s_run[nf][par] += __shfl_xor_sync(0xFFFFFFFF, s_run[nf][par], mask);

    __syncthreads();   // done reading Ps (mma2 of last chunk) before sums reuse? separate region, but keep ordering cheap
    if (g == 0) {
#pragma unroll
        for (int nf = 0; nf < 2; nf++)
#pragma unroll
            for (int par = 0; par < 2; par++)
                sums[(wid & 1) * 64 + wn + nf * 8 + 2 * tig + par] = s_run[nf][par];
    }
    __syncthreads();
    if (tid < 64) {
        float r = 1.0f / (sums[tid] + sums[64 + tid]);
        rcol[tid] = r;
        if (attn_out) g_rs[n * HW + j0 + tid] = r;
    }
    __syncthreads();

    if (!xout) return;
    float rj[2][2];
#pragma unroll
    for (int nf = 0; nf < 2; nf++)
#pragma unroll
        for (int par = 0; par < 2; par++)
            rj[nf][par] = rcol[wn + nf * 8 + 2 * tig + par];

    const float* qn = g_qn + (size_t)n * CHW;
    float* xp = xout + (size_t)n * CHW;
#pragma unroll
    for (int mf = 0; mf < 2; mf++) {
        int c = wm + mf * 16 + g;
#pragma unroll
        for (int nf = 0; nf < 2; nf++) {
            int j = j0 + wn + nf * 8 + 2 * tig;
            float2 q0 = *(const float2*)(qn + c * HW + j);
            float2 q1 = *(const float2*)(qn + (c + 8) * HW + j);
            *(float2*)(xp + c * HW + j) =
                make_float2(acc2[mf][nf][0] * rj[nf][0] + q0.x,
                            acc2[mf][nf][1] * rj[nf][1] + q0.y);
            *(float2*)(xp + (c + 8) * HW + j) =
                make_float2(acc2[mf][nf][2] * rj[nf][0] + q1.x,
                            acc2[mf][nf][3] * rj[nf][1] + q1.y);
        }
    }
}

// ---------------- 4. attn normalization: attn[n,i,j] *= rs[n,j] --------------
__global__ __launch_bounds__(256) void attn_norm_kernel(float* __restrict__ attn)
{
    int n = blockIdx.y;
    int i = blockIdx.x;
    float* row = attn + ((size_t)n * HW + i) * HW;
    const float* rs = g_rs + n * HW;
    int j4 = threadIdx.x * 4;
    float4 v = *(float4*)(row + j4);
    float4 r = *(const float4*)(rs + j4);
    v.x *= r.x; v.y *= r.y; v.z *= r.z; v.w *= r.w;
    *(float4*)(row + j4) = v;
}

// ---------------------------------------------------------------------------
extern "C" void kernel_launch(void* const* d_in, const int* in_sizes, int n_in,
                              void* d_out, int out_size)
{
    const float* query = (const float*)d_in[0];
    const float* key   = (const float*)d_in[1];
    const float* value = (const float*)d_in[2];
    const float* ln1w  = (const float*)d_in[3];
    const float* ln1b  = (const float*)d_in[4];
    const float* ln2w  = (const float*)d_in[5];
    const float* ln2b  = (const float*)d_in[6];
    const float* ln3w  = (const float*)d_in[7];
    const float* ln3b  = (const float*)d_in[8];
    const float* wq    = (const float*)d_in[9];
    const float* bq    = (const float*)d_in[10];
    const float* wk    = (const float*)d_in[11];
    const float* bk    = (const float*)d_in[12];
    const float* wv    = (const float*)d_in[13];
    const float* bv    = (const float*)d_in[14];

    float* out = (float*)d_out;
    const size_t XSZ = (size_t)NB * CHW;
    const size_t ASZ = (size_t)NB * HW * HW;

    float* x_out    = nullptr;
    float* attn_out = nullptr;
    size_t osz = (size_t)out_size;
    if (osz >= XSZ + ASZ)      { x_out = out; attn_out = out + XSZ; }
    else if (osz == ASZ)       { attn_out = out; }
    else                       { x_out = out; }

    static int attr_set = 0;
    const int PROJ_SMEM  = (64 * 68 + 256 * 68) * 4;   // 87040
    const int FLASH_SMEM = FLASH_U32 * 4;              // 90880
    if (!attr_set) {
        cudaFuncSetAttribute(proj_kernel,
                             cudaFuncAttributeMaxDynamicSharedMemorySize, PROJ_SMEM);
        cudaFuncSetAttribute(flash_kernel,
                             cudaFuncAttributeMaxDynamicSharedMemorySize, FLASH_SMEM);
        attr_set = 1;
    }

    ln_stats_kernel<<<dim3(96, 4), 256>>>(query, key, value);
    ln_apply_kernel<<<dim3(96, 4), 256>>>(query, key, value,
                                          ln1w, ln1b, ln2w, ln2b, ln3w, ln3b);
    proj_kernel<<<dim3(4, NB, 3), 256, PROJ_SMEM>>>(wq, bq, wk, bk, wv, bv);
    flash_kernel<<<dim3(HW / JT, NB), 256, FLASH_SMEM>>>(attn_out, x_out);
    if (attn_out)
        attn_norm_kernel<<<dim3(HW, NB), 256>>>(attn_out);
}

// round 10
// speedup vs baseline: 3.5582x; 1.1832x over previous
#include <cuda_runtime.h>
#include <math_constants.h>

#define NB  32
#define C   64
#define HW  1024
#define CHW 65536
#define EPS 1e-5f
#define JT  128
#define IC  64
#define LSCALE 0.180336880f   // 0.125 * log2(e)

// ---------------- scratch ----------------------------------------------------
__device__ float g_qn[NB * CHW];
__device__ float g_kn[NB * CHW];
__device__ float g_vn[NB * CHW];
__device__ float g_q [NB * CHW];           // tf32-rounded, pre-scaled by LSCALE
__device__ float g_kt[NB * CHW];           // K transposed [n][i][c], tf32-rounded
__device__ float g_v [NB * CHW];           // tf32-rounded
__device__ float g_part[96][4][2];         // LN partial sums

// ---------------- helpers ----------------------------------------------------
__device__ __forceinline__ unsigned f2tf(float x) {
    unsigned u;
    asm("cvt.rna.tf32.f32 %0, %1;" : "=r"(u) : "f"(x));
    return u;
}
__device__ __forceinline__ float ex2(float x) {
    float y;
    asm("ex2.approx.f32 %0, %1;" : "=f"(y) : "f"(x));
    return y;
}
__device__ __forceinline__ void mma_tf32(float* d, const unsigned* a, const unsigned* b) {
    asm volatile(
        "mma.sync.aligned.m16n8k8.row.col.f32.tf32.tf32.f32 "
        "{%0,%1,%2,%3}, {%4,%5,%6,%7}, {%8,%9}, {%0,%1,%2,%3};\n"
        : "+f"(d[0]), "+f"(d[1]), "+f"(d[2]), "+f"(d[3])
        : "r"(a[0]), "r"(a[1]), "r"(a[2]), "r"(a[3]), "r"(b[0]), "r"(b[1]));
}
__device__ __forceinline__ void cp16(unsigned dst, const void* src) {
    asm volatile("cp.async.cg.shared.global [%0], [%1], 16;" :: "r"(dst), "l"(src));
}
#define CP_COMMIT() asm volatile("cp.async.commit_group;")
#define CP_WAIT0()  asm volatile("cp.async.wait_group 0;")

// ---------------- 1a. LN stats: grid (96, 4), 256 thr -----------------------
__global__ __launch_bounds__(256) void ln_stats_kernel(
    const float* __restrict__ q, const float* __restrict__ k, const float* __restrict__ v)
{
    int t     = blockIdx.x;
    int quart = blockIdx.y;
    int which = t % 3, n = t / 3;
    const float* x = (which == 0 ? q : which == 1 ? k : v) + (size_t)n * CHW + quart * 16384;

    int tid = threadIdx.x;
    float4 a4 = make_float4(0, 0, 0, 0), q4 = make_float4(0, 0, 0, 0);
    for (int i = tid * 4; i < 16384; i += 256 * 4) {
        float4 val = *(const float4*)(x + i);
        a4.x += val.x; a4.y += val.y; a4.z += val.z; a4.w += val.w;
        q4.x += val.x * val.x; q4.y += val.y * val.y;
        q4.z += val.z * val.z; q4.w += val.w * val.w;
    }
    float s  = a4.x + a4.y + a4.z + a4.w;
    float ss = q4.x + q4.y + q4.z + q4.w;

    __shared__ float sm[256], sm2[256];
    sm[tid] = s; sm2[tid] = ss;
    __syncthreads();
    for (int o = 128; o > 0; o >>= 1) {
        if (tid < o) { sm[tid] += sm[tid + o]; sm2[tid] += sm2[tid + o]; }
        __syncthreads();
    }
    if (tid == 0) { g_part[t][quart][0] = sm[0]; g_part[t][quart][1] = sm2[0]; }
}

// ---------------- 1b. LN apply: grid (96, 4), 256 thr -----------------------
__global__ __launch_bounds__(256) void ln_apply_kernel(
    const float* __restrict__ q, const float* __restrict__ k, const float* __restrict__ v,
    const float* __restrict__ w1, const float* __restrict__ b1,
    const float* __restrict__ w2, const float* __restrict__ b2,
    const float* __restrict__ w3, const float* __restrict__ b3)
{
    int t     = blockIdx.x;
    int quart = blockIdx.y;
    int which = t % 3, n = t / 3;
    const float *x, *w, *b;
    float* dst;
    if (which == 0)      { x = q; w = w1; b = b1; dst = g_qn; }
    else if (which == 1) { x = k; w = w2; b = b2; dst = g_kn; }
    else                 { x = v; w = w3; b = b3; dst = g_vn; }
    size_t off = (size_t)n * CHW + quart * 16384;
    x += off; dst += off;
    w += quart * 16384; b += quart * 16384;

    float s = 0.f, ss = 0.f;
#pragma unroll
    for (int qq = 0; qq < 4; qq++) { s += g_part[t][qq][0]; ss += g_part[t][qq][1]; }
    float mean = s * (1.0f / CHW);
    float var  = ss * (1.0f / CHW) - mean * mean;
    float rstd = rsqrtf(var + EPS);

    int tid = threadIdx.x;
    for (int i = tid * 4; i < 16384; i += 256 * 4) {
        float4 val = *(const float4*)(x + i);
        float4 wv  = *(const float4*)(w + i);
        float4 bv  = *(const float4*)(b + i);
        float4 o4;
        o4.x = (val.x - mean) * rstd * wv.x + bv.x;
        o4.y = (val.y - mean) * rstd * wv.y + bv.y;
        o4.z = (val.z - mean) * rstd * wv.z + bv.z;
        o4.w = (val.w - mean) * rstd * wv.w + bv.w;
        *(float4*)(dst + i) = o4;
    }
}

// ---------------- 2. projection; outputs tf32-prerounded --------------------
__global__ __launch_bounds__(256) void proj_kernel(
    const float* __restrict__ wq, const float* __restrict__ bq,
    const float* __restrict__ wk, const float* __restrict__ bk,
    const float* __restrict__ wv, const float* __restrict__ bv)
{
    extern __shared__ unsigned psm[];
    unsigned* Ws = psm;              // [64 o][68]
    unsigned* Xs = psm + 64 * 68;    // [64 c][264]; T reuse needs 256*68

    int which = blockIdx.z;
    int n     = blockIdx.y;
    int p0    = blockIdx.x * 256;
    const float *src, *W, *B;
    if (which == 0)      { src = g_qn; W = wq; B = bq; }
    else if (which == 1) { src = g_kn; W = wk; B = bk; }
    else                 { src = g_vn; W = wv; B = bv; }
    src += (size_t)n * CHW;
    float wscale = (which == 0) ? LSCALE : 1.0f;

    int tid = threadIdx.x;
    for (int idx = tid; idx < 64 * 16; idx += 256) {
        int o = idx >> 4, c4 = (idx & 15) << 2;
        float4 v = *(const float4*)(W + o * C + c4);
        *(uint4*)(Ws + o * 68 + c4) =
            make_uint4(f2tf(v.x * wscale), f2tf(v.y * wscale),
                       f2tf(v.z * wscale), f2tf(v.w * wscale));
    }
    for (int idx = tid; idx < 64 * 64; idx += 256) {
        int c = idx >> 6, p4 = (idx & 63) << 2;
        float4 v = *(const float4*)(src + c * HW + p0 + p4);
        *(uint4*)(Xs + c * 264 + p4) =
            make_uint4(f2tf(v.x), f2tf(v.y), f2tf(v.z), f2tf(v.w));
    }
    __syncthreads();

    int wid = tid >> 5, lane = tid & 31;
    int g = lane >> 2, tig = lane & 3;
    int wn = wid * 32;

    float acc[4][4][4] = {};
#pragma unroll
    for (int kk = 0; kk < 8; kk++) {
        int c0 = kk * 8;
        unsigned a[4][4], b[4][2];
#pragma unroll
        for (int mf = 0; mf < 4; mf++) {
            int r = mf * 16 + g;
            a[mf][0] = Ws[r * 68 + c0 + tig];
            a[mf][1] = Ws[(r + 8) * 68 + c0 + tig];
            a[mf][2] = Ws[r * 68 + c0 + tig + 4];
            a[mf][3] = Ws[(r + 8) * 68 + c0 + tig + 4];
        }
#pragma unroll
        for (int nf = 0; nf < 4; nf++) {
            int col = wn + nf * 8 + g;
            b[nf][0] = Xs[(c0 + tig) * 264 + col];
            b[nf][1] = Xs[(c0 + tig + 4) * 264 + col];
        }
#pragma unroll
        for (int mf = 0; mf < 4; mf++)
#pragma unroll
            for (int nf = 0; nf < 4; nf++)
                mma_tf32(acc[mf][nf], a[mf], b[nf]);
    }

    if (which != 1) {
        float* dst = (which == 0 ? g_q : g_v) + (size_t)n * CHW;
#pragma unroll
        for (int mf = 0; mf < 4; mf++) {
            int o = mf * 16 + g;
            float b0 = B[o] * wscale, b1 = B[o + 8] * wscale;
#pragma unroll
            for (int nf = 0; nf < 4; nf++) {
                int p = p0 + wn + nf * 8 + 2 * tig;
                *(uint2*)(dst + o * HW + p) =
                    make_uint2(f2tf(acc[mf][nf][0] + b0), f2tf(acc[mf][nf][1] + b0));
                *(uint2*)(dst + (o + 8) * HW + p) =
                    make_uint2(f2tf(acc[mf][nf][2] + b1), f2tf(acc[mf][nf][3] + b1));
            }
        }
    } else {
        __syncthreads();
        float* T = (float*)Xs;   // [256 p][68]
#pragma unroll
        for (int mf = 0; mf < 4; mf++) {
            int o = mf * 16 + g;
            float b0 = B[o], b1 = B[o + 8];
#pragma unroll
            for (int nf = 0; nf < 4; nf++) {
                int p = wn + nf * 8 + 2 * tig;
                T[p * 68 + o]           = acc[mf][nf][0] + b0;
                T[(p + 1) * 68 + o]     = acc[mf][nf][1] + b0;
                T[p * 68 + o + 8]       = acc[mf][nf][2] + b1;
                T[(p + 1) * 68 + o + 8] = acc[mf][nf][3] + b1;
            }
        }
        __syncthreads();
        float* dst = g_kt + (size_t)n * CHW;
        for (int idx = tid; idx < 256 * 16; idx += 256) {
            int p = idx >> 4, c4 = (idx & 15) << 2;
            uint4 v = make_uint4(f2tf(T[p * 68 + c4]),     f2tf(T[p * 68 + c4 + 1]),
                                 f2tf(T[p * 68 + c4 + 2]), f2tf(T[p * 68 + c4 + 3]));
            *(uint4*)(dst + (size_t)(p0 + p) * C + c4) = v;
        }
    }
}

// ---------------- 3. flash: sum pass + normalized output pass ----------------
// grid = (8 jt, NB), block 256 (8 warps = 2 i-groups x 4 j-groups of 32x32)
// smem u32: QP[64*136]=8704 (Q staging then Ps[i][j]) | K0,K1[64*68] | V0,V1[64*68]
//           | sums 256 | rcol 128   => 26496 u32 = 105984 B
#define OFF_QP  0
#define OFF_K0  8704
#define OFF_K1  (8704 + 4352)
#define OFF_V0  (8704 + 8704)
#define OFF_V1  (8704 + 8704 + 4352)
#define OFF_SUM (8704 + 8704 + 8704)
#define OFF_RC  (OFF_SUM + 256)
#define FLASH_U32 (OFF_RC + 128)

__global__ __launch_bounds__(256, 1) void flash_kernel(
    float* __restrict__ attn_out, float* __restrict__ xout)
{
    extern __shared__ unsigned fsm[];
    unsigned* Qs  = fsm + OFF_QP;
    unsigned* Ps  = fsm + OFF_QP;
    float*    sums = (float*)(fsm + OFF_SUM);
    float*    rcol = (float*)(fsm + OFF_RC);

    int n  = blockIdx.y;
    int j0 = blockIdx.x * JT;
    int tid = threadIdx.x;
    const float* kt = g_kt + (size_t)n * CHW;
    const float* qp = g_q  + (size_t)n * CHW;
    const float* vp = g_v  + (size_t)n * CHW;

    unsigned sb = (unsigned)__cvta_generic_to_shared(fsm);

    int li[4], lc[4];
#pragma unroll
    for (int t = 0; t < 4; t++) {
        int idx = tid + t * 256;
        li[t] = idx >> 4; lc[t] = (idx & 15) << 2;
    }

    // preload K chunk 0 (Phase A)
#pragma unroll
    for (int t = 0; t < 4; t++)
        cp16(sb + ((OFF_K0 + li[t] * 68 + lc[t]) << 2), kt + (size_t)li[t] * C + lc[t]);
    CP_COMMIT();

    // Q staging [64 c][128 j] (tf32 bits, pre-scaled)
    for (int idx = tid; idx < 64 * 32; idx += 256) {
        int c = idx >> 5, j4 = (idx & 31) << 2;
        *(uint4*)(Qs + c * 136 + j4) = *(const uint4*)(qp + c * HW + j0 + j4);
    }
    __syncthreads();

    int wid = tid >> 5, lane = tid & 31;
    int g = lane >> 2, tig = lane & 3;
    int wm = (wid & 1) * 32;         // i (mma1) / c (mma2) group
    int wj = (wid >> 1) * 32;        // j group

    // Q fragments (64 regs)
    unsigned Qb[8][4][2];
#pragma unroll
    for (int kk = 0; kk < 8; kk++)
#pragma unroll
        for (int nf = 0; nf < 4; nf++) {
            int col = wj + nf * 8 + g;
            Qb[kk][nf][0] = Qs[(kk * 8 + tig) * 136 + col];
            Qb[kk][nf][1] = Qs[(kk * 8 + tig + 4) * 136 + col];
        }
    __syncthreads();   // Qs free for Ps reuse

    // ---------------- Phase A: column sums of exp2(logits) -------------------
    float s_run[4][2];
#pragma unroll
    for (int nf = 0; nf < 4; nf++) { s_run[nf][0] = 0.f; s_run[nf][1] = 0.f; }

    for (int ch = 0; ch < 16; ch++) {
        CP_WAIT0();
        __syncthreads();
        if (ch < 15) {
            int i0n = (ch + 1) * IC;
            unsigned koff = ((ch + 1) & 1) ? OFF_K1 : OFF_K0;
#pragma unroll
            for (int t = 0; t < 4; t++)
                cp16(sb + ((koff + li[t] * 68 + lc[t]) << 2),
                     kt + (size_t)(i0n + li[t]) * C + lc[t]);
            CP_COMMIT();
        }
        unsigned* Ks = fsm + ((ch & 1) ? OFF_K1 : OFF_K0);

        float acc1[2][4][4] = {};
#pragma unroll
        for (int kk = 0; kk < 8; kk++) {
            int c0 = kk * 8;
            unsigned a[2][4];
#pragma unroll
            for (int mf = 0; mf < 2; mf++) {
                int r = wm + mf * 16 + g;
                a[mf][0] = Ks[r * 68 + c0 + tig];
                a[mf][1] = Ks[(r + 8) * 68 + c0 + tig];
                a[mf][2] = Ks[r * 68 + c0 + tig + 4];
                a[mf][3] = Ks[(r + 8) * 68 + c0 + tig + 4];
            }
#pragma unroll
            for (int mf = 0; mf < 2; mf++)
#pragma unroll
                for (int nf = 0; nf < 4; nf++)
                    mma_tf32(acc1[mf][nf], a[mf], Qb[kk][nf]);
        }
#pragma unroll
        for (int mf = 0; mf < 2; mf++)
#pragma unroll
            for (int nf = 0; nf < 4; nf++) {
                s_run[nf][0] += ex2(acc1[mf][nf][0]) + ex2(acc1[mf][nf][2]);
                s_run[nf][1] += ex2(acc1[mf][nf][1]) + ex2(acc1[mf][nf][3]);
            }
    }

    // reduce over g-lanes, then across the 2 i-groups via smem
#pragma unroll
    for (int mask = 4; mask <= 16; mask <<= 1)
#pragma unroll
        for (int nf = 0; nf < 4; nf++)
#pragma unroll
            for (int par = 0; par < 2; par++)
                s_run[nf][par] += __shfl_xor_sync(0xFFFFFFFF, s_run[nf][par], mask);

    if (g == 0) {
#pragma unroll
        for (int nf = 0; nf < 4; nf++)
#pragma unroll
            for (int par = 0; par < 2; par++)
                sums[(wid & 1) * 128 + wj + nf * 8 + 2 * tig + par] = s_run[nf][par];
    }
    __syncthreads();
    if (tid < 128) rcol[tid] = 1.0f / (sums[tid] + sums[128 + tid]);

    // prefetch Phase B chunk 0 (K + V) while rcol settles
#pragma unroll
    for (int t = 0; t < 4; t++) {
        cp16(sb + ((OFF_K0 + li[t] * 68 + lc[t]) << 2), kt + (size_t)li[t] * C + lc[t]);
        cp16(sb + ((OFF_V0 + li[t] * 68 + lc[t]) << 2), vp + li[t] * HW + lc[t]);
    }
    CP_COMMIT();
    __syncthreads();

    float rj[4][2];
#pragma unroll
    for (int nf = 0; nf < 4; nf++)
#pragma unroll
        for (int par = 0; par < 2; par++)
            rj[nf][par] = rcol[wj + nf * 8 + 2 * tig + par];

    // ---------------- Phase B: normalized probs + V@P ------------------------
    float* ap = attn_out ? attn_out + (size_t)n * HW * HW + j0 : nullptr;
    float acc2[2][4][4] = {};

    for (int ch = 0; ch < 16; ch++) {
        CP_WAIT0();
        __syncthreads();
        if (ch < 15) {
            int i0n = (ch + 1) * IC;
            unsigned koff = ((ch + 1) & 1) ? OFF_K1 : OFF_K0;
            unsigned voff = ((ch + 1) & 1) ? OFF_V1 : OFF_V0;
#pragma unroll
            for (int t = 0; t < 4; t++) {
                cp16(sb + ((koff + li[t] * 68 + lc[t]) << 2),
                     kt + (size_t)(i0n + li[t]) * C + lc[t]);
                cp16(sb + ((voff + li[t] * 68 + lc[t]) << 2),
                     vp + li[t] * HW + i0n + lc[t]);
            }
            CP_COMMIT();
        }
        unsigned* Ks = fsm + ((ch & 1) ? OFF_K1 : OFF_K0);
        unsigned* Vs = fsm + ((ch & 1) ? OFF_V1 : OFF_V0);
        int i0 = ch * IC;

        float acc1[2][4][4] = {};
#pragma unroll
        for (int kk = 0; kk < 8; kk++) {
            int c0 = kk * 8;
            unsigned a[2][4];
#pragma unroll
            for (int mf = 0; mf < 2; mf++) {
                int r = wm + mf * 16 + g;
                a[mf][0] = Ks[r * 68 + c0 + tig];
                a[mf][1] = Ks[(r + 8) * 68 + c0 + tig];
                a[mf][2] = Ks[r * 68 + c0 + tig + 4];
                a[mf][3] = Ks[(r + 8) * 68 + c0 + tig + 4];
            }
#pragma unroll
            for (int mf = 0; mf < 2; mf++)
#pragma unroll
                for (int nf = 0; nf < 4; nf++)
                    mma_tf32(acc1[mf][nf], a[mf], Qb[kk][nf]);
        }

        // normalized probs: STG + STS(tf32)
#pragma unroll
        for (int mf = 0; mf < 2; mf++) {
            int il = wm + mf * 16 + g;
#pragma unroll
            for (int nf = 0; nf < 4; nf++) {
                int col = wj + nf * 8 + 2 * tig;
                float p0 = ex2(acc1[mf][nf][0]) * rj[nf][0];
                float p1 = ex2(acc1[mf][nf][1]) * rj[nf][1];
                float p2 = ex2(acc1[mf][nf][2]) * rj[nf][0];
                float p3 = ex2(acc1[mf][nf][3]) * rj[nf][1];
                if (ap) {
                    *(float2*)(ap + (size_t)(i0 + il) * HW + col)     = make_float2(p0, p1);
                    *(float2*)(ap + (size_t)(i0 + il + 8) * HW + col) = make_float2(p2, p3);
                }
                *(uint2*)(Ps + il * 136 + col)       = make_uint2(f2tf(p0), f2tf(p1));
                *(uint2*)(Ps + (il + 8) * 136 + col) = make_uint2(f2tf(p2), f2tf(p3));
            }
        }
        __syncthreads();   // Ps complete

        if (xout) {
#pragma unroll
            for (int kk = 0; kk < 8; kk++) {
                int k0 = kk * 8;
                unsigned a[2][4], b[4][2];
#pragma unroll
                for (int mf = 0; mf < 2; mf++) {
                    int r = wm + mf * 16 + g;   // c row
                    a[mf][0] = Vs[r * 68 + k0 + tig];
                    a[mf][1] = Vs[(r + 8) * 68 + k0 + tig];
                    a[mf][2] = Vs[r * 68 + k0 + tig + 4];
                    a[mf][3] = Vs[(r + 8) * 68 + k0 + tig + 4];
                }
#pragma unroll
                for (int nf = 0; nf < 4; nf++) {
                    int col = wj + nf * 8 + g;
                    b[nf][0] = Ps[(k0 + tig) * 136 + col];
                    b[nf][1] = Ps[(k0 + tig + 4) * 136 + col];
                }
#pragma unroll
                for (int mf = 0; mf < 2; mf++)
#pragma unroll
                    for (int nf = 0; nf < 4; nf++)
                        mma_tf32(acc2[mf][nf], a[mf], b[nf]);
            }
        }
    }

    if (!xout) return;
    const float* qn = g_qn + (size_t)n * CHW;
    float* xp = xout + (size_t)n * CHW;
#pragma unroll
    for (int mf = 0; mf < 2; mf++) {
        int c = wm + mf * 16 + g;
#pragma unroll
        for (int nf = 0; nf < 4; nf++) {
            int j = j0 + wj + nf * 8 + 2 * tig;
            float2 q0 = *(const float2*)(qn + c * HW + j);
            float2 q1 = *(const float2*)(qn + (c + 8) * HW + j);
            *(float2*)(xp + c * HW + j) =
                make_float2(acc2[mf][nf][0] + q0.x, acc2[mf][nf][1] + q0.y);
            *(float2*)(xp + (c + 8) * HW + j) =
                make_float2(acc2[mf][nf][2] + q1.x, acc2[mf][nf][3] + q1.y);
        }
    }
}

// ---------------------------------------------------------------------------
extern "C" void kernel_launch(void* const* d_in, const int* in_sizes, int n_in,
                              void* d_out, int out_size)
{
    const float* query = (const float*)d_in[0];
    const float* key   = (const float*)d_in[1];
    const float* value = (const float*)d_in[2];
    const float* ln1w  = (const float*)d_in[3];
    const float* ln1b  = (const float*)d_in[4];
    const float* ln2w  = (const float*)d_in[5];
    const float* ln2b  = (const float*)d_in[6];
    const float* ln3w  = (const float*)d_in[7];
    const float* ln3b  = (const float*)d_in[8];
    const float* wq    = (const float*)d_in[9];
    const float* bq    = (const float*)d_in[10];
    const float* wk    = (const float*)d_in[11];
    const float* bk    = (const float*)d_in[12];
    const float* wv    = (const float*)d_in[13];
    const float* bv    = (const float*)d_in[14];

    float* out = (float*)d_out;
    const size_t XSZ = (size_t)NB * CHW;
    const size_t ASZ = (size_t)NB * HW * HW;

    float* x_out    = nullptr;
    float* attn_out = nullptr;
    size_t osz = (size_t)out_size;
    if (osz >= XSZ + ASZ)      { x_out = out; attn_out = out + XSZ; }
    else if (osz == ASZ)       { attn_out = out; }
    else                       { x_out = out; }

    static int attr_set = 0;
    const int PROJ_SMEM  = (64 * 68 + 256 * 68) * 4;   // 87040
    const int FLASH_SMEM = FLASH_U32 * 4;              // 105984
    if (!attr_set) {
        cudaFuncSetAttribute(proj_kernel,
                             cudaFuncAttributeMaxDynamicSharedMemorySize, PROJ_SMEM);
        cudaFuncSetAttribute(flash_kernel,
                             cudaFuncAttributeMaxDynamicSharedMemorySize, FLASH_SMEM);
        attr_set = 1;
    }

    ln_stats_kernel<<<dim3(96, 4), 256>>>(query, key, value);
    ln_apply_kernel<<<dim3(96, 4), 256>>>(query, key, value,
                                          ln1w, ln1b, ln2w, ln2b, ln3w, ln3b);
    proj_kernel<<<dim3(4, NB, 3), 256, PROJ_SMEM>>>(wq, bq, wk, bk, wv, bv);
    flash_kernel<<<dim3(HW / JT, NB), 256, FLASH_SMEM>>>(attn_out, x_out);
}